// round 14
// baseline (speedup 1.0000x reference)
#include <cuda_runtime.h>
#include <cuda_fp16.h>
#include <math.h>
#include <stdint.h>

#define TT    4096      // BATCH * SEQ tokens
#define HID   4096
#define NH    32
#define NKV   8
#define HD    128
#define QKVD  6144      // (32 + 16) * 128
#define SEQ   1024
#define NB    4

// Scratch (static device globals; no runtime allocation)
__device__ float g_qkv[(size_t)TT * QKVD];   // 96 MB
// activations: fp16 hi/lo split.  weights: single fp16 (rn).
__device__ __half g_hshi[(size_t)TT * HID];
__device__ __half g_hslo[(size_t)TT * HID];
__device__ __half g_wq[(size_t)QKVD * HID];
__device__ __half g_wo[(size_t)HID * HID];
__device__ __half g_atthi[(size_t)TT * HID];
__device__ __half g_attlo[(size_t)TT * HID];
// split fp16 q/k/v (head-major)
__device__ __half g_qhi[(size_t)NB * NH * SEQ * HD];
__device__ __half g_qlo[(size_t)NB * NH * SEQ * HD];
__device__ __half g_khi[(size_t)NB * NKV * SEQ * HD];
__device__ __half g_klo[(size_t)NB * NKV * SEQ * HD];
__device__ __half g_vhi[(size_t)NB * NKV * SEQ * HD];
__device__ __half g_vlo[(size_t)NB * NKV * SEQ * HD];

// ===========================================================================
// helpers
// ===========================================================================
__device__ __forceinline__ uint32_t smem_u32(const void* p) {
    uint32_t a;
    asm("{ .reg .u64 t; cvta.to.shared.u64 t, %1; cvt.u32.u64 %0, t; }"
        : "=r"(a) : "l"(p));
    return a;
}
__device__ __forceinline__ void ldsm_x4(uint32_t* r, uint32_t addr) {
    asm volatile("ldmatrix.sync.aligned.m8n8.x4.shared.b16 {%0,%1,%2,%3}, [%4];"
                 : "=r"(r[0]), "=r"(r[1]), "=r"(r[2]), "=r"(r[3]) : "r"(addr));
}
__device__ __forceinline__ void ldsm_x4_t(uint32_t* r, uint32_t addr) {
    asm volatile("ldmatrix.sync.aligned.m8n8.x4.trans.shared.b16 {%0,%1,%2,%3}, [%4];"
                 : "=r"(r[0]), "=r"(r[1]), "=r"(r[2]), "=r"(r[3]) : "r"(addr));
}
__device__ __forceinline__ void mma_f16(float* c, const uint32_t* a,
                                        uint32_t b0, uint32_t b1) {
    asm volatile(
        "mma.sync.aligned.m16n8k16.row.col.f32.f16.f16.f32 "
        "{%0,%1,%2,%3}, {%4,%5,%6,%7}, {%8,%9}, {%0,%1,%2,%3};"
        : "+f"(c[0]), "+f"(c[1]), "+f"(c[2]), "+f"(c[3])
        : "r"(a[0]), "r"(a[1]), "r"(a[2]), "r"(a[3]), "r"(b0), "r"(b1));
}
__device__ __forceinline__ void cp16(uint32_t dst, const void* src) {
    asm volatile("cp.async.cg.shared.global [%0], [%1], 16;" :: "r"(dst), "l"(src));
}
#define CP_COMMIT() asm volatile("cp.async.commit_group;" ::: "memory")
#define CP_WAIT0()  asm volatile("cp.async.wait_group 0;" ::: "memory")
#define CP_WAIT1()  asm volatile("cp.async.wait_group 1;" ::: "memory")

__device__ __forceinline__ uint32_t h2_as_u32(__half2 h) {
    return *reinterpret_cast<uint32_t*>(&h);
}

// ===========================================================================
// split2h: fp32 -> fp16 hi (rn) + fp16 lo (rn residual).  8 elems/thread.
// ===========================================================================
__global__ __launch_bounds__(256) void split2h(const float* __restrict__ src,
                                               __half* __restrict__ hi,
                                               __half* __restrict__ lo,
                                               int n8) {
    int i = blockIdx.x * 256 + threadIdx.x;
    if (i >= n8) return;
    const float4* s = reinterpret_cast<const float4*>(src) + (size_t)i * 2;
    float4 f0 = s[0], f1 = s[1];
    __half2 h0 = __floats2half2_rn(f0.x, f0.y);
    __half2 h1 = __floats2half2_rn(f0.z, f0.w);
    __half2 h2 = __floats2half2_rn(f1.x, f1.y);
    __half2 h3 = __floats2half2_rn(f1.z, f1.w);
    __half2 l0 = __floats2half2_rn(f0.x - __low2float(h0), f0.y - __high2float(h0));
    __half2 l1 = __floats2half2_rn(f0.z - __low2float(h1), f0.w - __high2float(h1));
    __half2 l2 = __floats2half2_rn(f1.x - __low2float(h2), f1.y - __high2float(h2));
    __half2 l3 = __floats2half2_rn(f1.z - __low2float(h3), f1.w - __high2float(h3));
    *reinterpret_cast<uint4*>(hi + (size_t)i * 8) =
        make_uint4(h2_as_u32(h0), h2_as_u32(h1), h2_as_u32(h2), h2_as_u32(h3));
    *reinterpret_cast<uint4*>(lo + (size_t)i * 8) =
        make_uint4(h2_as_u32(l0), h2_as_u32(l1), h2_as_u32(l2), h2_as_u32(l3));
}

// convh: fp32 -> single fp16 rn (weights).  8 elems/thread.
__global__ __launch_bounds__(256) void convh(const float* __restrict__ src,
                                             __half* __restrict__ dst, int n8) {
    int i = blockIdx.x * 256 + threadIdx.x;
    if (i >= n8) return;
    const float4* s = reinterpret_cast<const float4*>(src) + (size_t)i * 2;
    float4 f0 = s[0], f1 = s[1];
    __half2 h0 = __floats2half2_rn(f0.x, f0.y);
    __half2 h1 = __floats2half2_rn(f0.z, f0.w);
    __half2 h2 = __floats2half2_rn(f1.x, f1.y);
    __half2 h3 = __floats2half2_rn(f1.z, f1.w);
    *reinterpret_cast<uint4*>(dst + (size_t)i * 8) =
        make_uint4(h2_as_u32(h0), h2_as_u32(h1), h2_as_u32(h2), h2_as_u32(h3));
}

// ===========================================================================
// gemm_fp16x2 (NT): C = (Ahi+Alo) @ B^T, fp16 in, fp32 out.  2 products:
// ah*b + al*b (A = activations split rn, B = weights single rn).
// BK=64, 3-stage cp.async pipeline, register-double-buffered fragments,
// product-major MMA ordering.  256 threads, 8 warps (4Mx2N), warp 32x64.
// ===========================================================================
#define GBM 128
#define GBN 128
#define GKB 64
#define GSTR 72                        // element stride (144B row)
#define GTILEB (128 * GSTR * 2)        // 18432 B per tensor tile
#define GSTAGEB (3 * GTILEB)           // 55296 B per stage (Ahi|Alo|B)
#define GEMM_SMEM (3 * GSTAGEB)        // 165888 B

__global__ __launch_bounds__(256, 1) void gemm_fp16x2(
        const __half* __restrict__ Ahi, const __half* __restrict__ Alo,
        const __half* __restrict__ B,
        float* __restrict__ C, int M, int N, int K) {
    extern __shared__ char sm8[];
    const uint32_t sb = smem_u32(sm8);
    const int tid = threadIdx.x;
    const int wid = tid >> 5;
    const int lane = tid & 31;
    const int wm = wid & 3;
    const int wn = wid >> 2;
    const int bm = blockIdx.y * GBM;
    const int bn = blockIdx.x * GBN;

    float acc[2][8][4];
#pragma unroll
    for (int i = 0; i < 2; i++)
#pragma unroll
        for (int j = 0; j < 8; j++)
#pragma unroll
            for (int q = 0; q < 4; q++) acc[i][j][q] = 0.f;

    const uint32_t aOffB = ((wm * 32 + (lane & 15)) * GSTR + (lane >> 4) * 8) * 2;
    const uint32_t bOffB = ((wn * 64 + (lane & 7) + ((lane >> 4) & 1) * 8) * GSTR
                           + ((lane >> 3) & 1) * 8) * 2;

    const int r0 = tid >> 3;                 // rows r0, r0+32, r0+64, r0+96
    const int cc0 = tid & 7;

    auto load_stage = [&](uint32_t base, int k0) {
#pragma unroll
        for (int u = 0; u < 4; ++u) {
            int row = r0 + u * 32;
            uint32_t d = base + row * (GSTR * 2) + cc0 * 16;
            size_t ao = (size_t)(bm + row) * K + k0 + cc0 * 8;
            size_t bo = (size_t)(bn + row) * K + k0 + cc0 * 8;
            cp16(d, Ahi + ao);
            cp16(d + GTILEB, Alo + ao);
            cp16(d + 2 * GTILEB, B + bo);
        }
    };

    const int NC = K / GKB;

    load_stage(sb, 0);
    CP_COMMIT();
    load_stage(sb + GSTAGEB, GKB);
    CP_COMMIT();

    int scur = 0, snext = 2;

    for (int kc = 0; kc < NC; ++kc) {
        if (kc == NC - 1) { CP_WAIT0(); } else { CP_WAIT1(); }
        __syncthreads();
        if (kc + 2 < NC) {
            load_stage(sb + snext * GSTAGEB, (kc + 2) * GKB);
            CP_COMMIT();
        }
        const uint32_t base = sb + scur * GSTAGEB;
        scur = (scur == 2) ? 0 : scur + 1;
        snext = (snext == 2) ? 0 : snext + 1;

        uint32_t ah[2][2][4], al[2][2][4], bh[2][4][4];

#pragma unroll
        for (int mt = 0; mt < 2; ++mt) {
            uint32_t aa = base + aOffB + mt * (16 * GSTR * 2);
            ldsm_x4(ah[0][mt], aa);
            ldsm_x4(al[0][mt], aa + GTILEB);
        }
#pragma unroll
        for (int p = 0; p < 4; ++p) {
            uint32_t ba = base + 2 * GTILEB + bOffB + p * (16 * GSTR * 2);
            ldsm_x4(bh[0][p], ba);
        }

#pragma unroll
        for (int ks = 0; ks < 4; ++ks) {
            const int cur = ks & 1, nxt = cur ^ 1;
            if (ks < 3) {
                const uint32_t ko = (ks + 1) * 32;
#pragma unroll
                for (int mt = 0; mt < 2; ++mt) {
                    uint32_t aa = base + aOffB + mt * (16 * GSTR * 2) + ko;
                    ldsm_x4(ah[nxt][mt], aa);
                    ldsm_x4(al[nxt][mt], aa + GTILEB);
                }
#pragma unroll
                for (int p = 0; p < 4; ++p) {
                    uint32_t ba = base + 2 * GTILEB + bOffB + p * (16 * GSTR * 2) + ko;
                    ldsm_x4(bh[nxt][p], ba);
                }
            }
            // product-major: 2 passes (ah*b, then al*b), no dependent chains
#pragma unroll
            for (int prod = 0; prod < 2; ++prod) {
#pragma unroll
                for (int p = 0; p < 4; ++p)
#pragma unroll
                    for (int n2 = 0; n2 < 2; ++n2) {
                        const int nt = p * 2 + n2;
                        uint32_t b0 = bh[cur][p][n2 * 2];
                        uint32_t b1 = bh[cur][p][n2 * 2 + 1];
#pragma unroll
                        for (int mt = 0; mt < 2; ++mt) {
                            const uint32_t* af = (prod == 1) ? al[cur][mt] : ah[cur][mt];
                            mma_f16(acc[mt][nt], af, b0, b1);
                        }
                    }
            }
        }
    }

    const int g = lane >> 2;
    const int cc = (lane & 3) * 2;
#pragma unroll
    for (int mt = 0; mt < 2; ++mt) {
        int rowc = bm + wm * 32 + mt * 16 + g;
#pragma unroll
        for (int nt = 0; nt < 8; ++nt) {
            int col = bn + wn * 64 + nt * 8 + cc;
            *reinterpret_cast<float2*>(&C[(size_t)rowc * N + col]) =
                make_float2(acc[mt][nt][0], acc[mt][nt][1]);
            *reinterpret_cast<float2*>(&C[(size_t)(rowc + 8) * N + col]) =
                make_float2(acc[mt][nt][2], acc[mt][nt][3]);
        }
    }
}

// ===========================================================================
// fused RoPE + head-major split to fp16 hi/lo (rn).  Q gets 128^-0.5 folded.
// ===========================================================================
__global__ __launch_bounds__(256) void rope_split(const float* __restrict__ qkv,
        __half* __restrict__ qhi, __half* __restrict__ qlo,
        __half* __restrict__ khi, __half* __restrict__ klo,
        __half* __restrict__ vhi, __half* __restrict__ vlo) {
    int x = blockIdx.x * 256 + threadIdx.x;
    int i = x & 63;
    int r = x >> 6;
    int hh = r % (NH + 2 * NKV);
    int t = r / (NH + 2 * NKV);
    int b = t >> 10;
    int s = t & (SEQ - 1);

    const float* base = qkv + (size_t)t * QKVD + hh * HD;
    float x1 = base[i];
    float x2 = base[i + 64];
    float y1, y2;
    if (hh < NH + NKV) {
        const float L2T = 13.287712379549449f;   // log2(10000)
        float invf = exp2f(-(float)(2 * i) * (1.0f / (float)HD) * L2T);
        float ang = (float)s * invf;
        float sn, cs;
        sincosf(ang, &sn, &cs);
        y1 = x1 * cs - x2 * sn;
        y2 = x2 * cs + x1 * sn;
    } else { y1 = x1; y2 = x2; }

    __half *dh, *dl;
    size_t off;
    if (hh < NH) {
        const float sc = 0.08838834764831845f;
        y1 *= sc; y2 *= sc;
        off = ((size_t)(b * NH + hh) * SEQ + s) * HD;
        dh = qhi; dl = qlo;
    } else if (hh < NH + NKV) {
        off = ((size_t)(b * NKV + (hh - NH)) * SEQ + s) * HD;
        dh = khi; dl = klo;
    } else {
        off = ((size_t)(b * NKV + (hh - NH - NKV)) * SEQ + s) * HD;
        dh = vhi; dl = vlo;
    }
    __half h1 = __float2half_rn(y1);
    __half h2 = __float2half_rn(y2);
    dh[off + i]      = h1;
    dh[off + i + 64] = h2;
    dl[off + i]      = __float2half_rn(y1 - __half2float(h1));
    dl[off + i + 64] = __float2half_rn(y2 - __half2float(h2));
}

// ===========================================================================
// Tensor-core causal GQA flash attention (fp16x3 split — extra accurate).
// Epilogue writes split fp16 hi/lo directly (feeds O-proj GEMM A side).
// ===========================================================================
#define AQ   128
#define AKT  64
#define ASTR 136
#define Q_BYTES   (AQ * ASTR * 2)
#define KV_BYTES  (AKT * ASTR * 2)
#define KVBUF     (4 * KV_BYTES)
#define ATT_SMEM  (2 * Q_BYTES + 2 * KVBUF)

__global__ __launch_bounds__(256) void attn_mma(
        const __half* __restrict__ Qhi, const __half* __restrict__ Qlo,
        const __half* __restrict__ Khi, const __half* __restrict__ Klo,
        const __half* __restrict__ Vhi, const __half* __restrict__ Vlo,
        __half* __restrict__ Ohi, __half* __restrict__ Olo) {
    extern __shared__ char sm8[];
    const uint32_t sb = smem_u32(sm8);
    const int tid = threadIdx.x, wid = tid >> 5, lane = tid & 31;
    const int qtile = gridDim.x - 1 - blockIdx.x;
    const int h = blockIdx.y, b = blockIdx.z;
    const int kvh = h >> 2;

    const size_t qbase = ((size_t)(b * NH + h) * SEQ + qtile * AQ) * HD;
    const size_t kbase = ((size_t)(b * NKV + kvh) * SEQ) * HD;

    for (int i = tid; i < AQ * 16; i += 256) {
        int row = i >> 4, c = i & 15;
        uint32_t d = sb + row * (ASTR * 2) + c * 16;
        const size_t src = qbase + (size_t)row * HD + c * 8;
        cp16(d, Qhi + src);
        cp16(d + Q_BYTES, Qlo + src);
    }
    {
        uint32_t dst0 = sb + 2 * Q_BYTES;
        for (int i = tid; i < AKT * 16; i += 256) {
            int row = i >> 4, c = i & 15;
            uint32_t d = dst0 + row * (ASTR * 2) + c * 16;
            const size_t src = kbase + (size_t)row * HD + c * 8;
            cp16(d,                Khi + src);
            cp16(d + KV_BYTES,     Klo + src);
            cp16(d + 2 * KV_BYTES, Vhi + src);
            cp16(d + 3 * KV_BYTES, Vlo + src);
        }
    }
    CP_COMMIT();

    float oacc[16][4];
#pragma unroll
    for (int n = 0; n < 16; n++)
#pragma unroll
        for (int q = 0; q < 4; q++) oacc[n][q] = 0.f;
    float m0 = -1e30f, m1 = -1e30f, l0 = 0.f, l1 = 0.f;

    const uint32_t aRow = wid * 16 + (lane & 15);
    const uint32_t aColP = (lane >> 4) * 8;
    const uint32_t qAddr = sb + (aRow * ASTR + aColP) * 2;
    const uint32_t bRowP = (lane & 7) + ((lane >> 4) & 1) * 8;
    const uint32_t bColP = ((lane >> 3) & 1) * 8;
    const uint32_t vRowP = (lane & 7) + ((lane >> 3) & 1) * 8;
    const uint32_t vColP = (lane >> 4) * 8;

    const int nkt = 2 * qtile + 2;
    const int row0g = qtile * AQ + wid * 16 + (lane >> 2);

    for (int kt = 0; kt < nkt; ++kt) {
        const int s = kt & 1;
        CP_WAIT0();
        __syncthreads();
        if (kt + 1 < nkt) {
            uint32_t dst0 = sb + 2 * Q_BYTES + (s ^ 1) * KVBUF;
            const size_t kvoff = kbase + (size_t)(kt + 1) * AKT * HD;
            for (int i = tid; i < AKT * 16; i += 256) {
                int row = i >> 4, c = i & 15;
                uint32_t d = dst0 + row * (ASTR * 2) + c * 16;
                const size_t src = kvoff + (size_t)row * HD + c * 8;
                cp16(d,                Khi + src);
                cp16(d + KV_BYTES,     Klo + src);
                cp16(d + 2 * KV_BYTES, Vhi + src);
                cp16(d + 3 * KV_BYTES, Vlo + src);
            }
            CP_COMMIT();
        }

        const uint32_t kvb = sb + 2 * Q_BYTES + s * KVBUF;

        float sacc[8][4];
#pragma unroll
        for (int n = 0; n < 8; n++)
#pragma unroll
            for (int q = 0; q < 4; q++) sacc[n][q] = 0.f;

#pragma unroll
        for (int ks = 0; ks < 8; ++ks) {
            uint32_t aq[4], aql[4];
            uint32_t qa = qAddr + ks * 32;
            ldsm_x4(aq, qa);
            ldsm_x4(aql, qa + Q_BYTES);
            uint32_t bh[4][4], bl[4][4];
#pragma unroll
            for (int p = 0; p < 4; ++p) {
                uint32_t ba = kvb + ((p * 16 + bRowP) * ASTR + ks * 16 + bColP) * 2;
                ldsm_x4(bh[p], ba);
                ldsm_x4(bl[p], ba + KV_BYTES);
            }
#pragma unroll
            for (int nt = 0; nt < 8; ++nt) {
                uint32_t h0 = bh[nt >> 1][(nt & 1) * 2];
                uint32_t h1 = bh[nt >> 1][(nt & 1) * 2 + 1];
                uint32_t q0 = bl[nt >> 1][(nt & 1) * 2];
                uint32_t q1 = bl[nt >> 1][(nt & 1) * 2 + 1];
                mma_f16(sacc[nt], aq, h0, h1);
                mma_f16(sacc[nt], aq, q0, q1);
                mma_f16(sacc[nt], aql, h0, h1);
            }
        }

        if (kt * AKT + AKT - 1 > qtile * AQ + wid * 16) {
            const int colb = kt * AKT + (lane & 3) * 2;
#pragma unroll
            for (int nt = 0; nt < 8; ++nt) {
                int c0 = colb + nt * 8;
                if (c0 > row0g)         sacc[nt][0] = -1e30f;
                if (c0 + 1 > row0g)     sacc[nt][1] = -1e30f;
                if (c0 > row0g + 8)     sacc[nt][2] = -1e30f;
                if (c0 + 1 > row0g + 8) sacc[nt][3] = -1e30f;
            }
        }

        float mx0 = -1e30f, mx1 = -1e30f;
#pragma unroll
        for (int nt = 0; nt < 8; ++nt) {
            mx0 = fmaxf(mx0, fmaxf(sacc[nt][0], sacc[nt][1]));
            mx1 = fmaxf(mx1, fmaxf(sacc[nt][2], sacc[nt][3]));
        }
        mx0 = fmaxf(mx0, __shfl_xor_sync(0xffffffffu, mx0, 1));
        mx0 = fmaxf(mx0, __shfl_xor_sync(0xffffffffu, mx0, 2));
        mx1 = fmaxf(mx1, __shfl_xor_sync(0xffffffffu, mx1, 1));
        mx1 = fmaxf(mx1, __shfl_xor_sync(0xffffffffu, mx1, 2));
        float nm0 = fmaxf(m0, mx0), nm1 = fmaxf(m1, mx1);
        float r0 = 0.f, r1 = 0.f;
#pragma unroll
        for (int nt = 0; nt < 8; ++nt) {
            sacc[nt][0] = __expf(sacc[nt][0] - nm0);
            sacc[nt][1] = __expf(sacc[nt][1] - nm0);
            sacc[nt][2] = __expf(sacc[nt][2] - nm1);
            sacc[nt][3] = __expf(sacc[nt][3] - nm1);
            r0 += sacc[nt][0] + sacc[nt][1];
            r1 += sacc[nt][2] + sacc[nt][3];
        }
        r0 += __shfl_xor_sync(0xffffffffu, r0, 1);
        r0 += __shfl_xor_sync(0xffffffffu, r0, 2);
        r1 += __shfl_xor_sync(0xffffffffu, r1, 1);
        r1 += __shfl_xor_sync(0xffffffffu, r1, 2);
        float a0 = __expf(m0 - nm0), a1 = __expf(m1 - nm1);
        l0 = l0 * a0 + r0;
        l1 = l1 * a1 + r1;
        m0 = nm0; m1 = nm1;
#pragma unroll
        for (int n = 0; n < 16; ++n) {
            oacc[n][0] *= a0; oacc[n][1] *= a0;
            oacc[n][2] *= a1; oacc[n][3] *= a1;
        }

        // ---- pack P (fp16 rn hi + rn residual lo) ----
        uint32_t ph[8][2], pl[8][2];
#pragma unroll
        for (int nt = 0; nt < 8; ++nt) {
            __half2 h01 = __floats2half2_rn(sacc[nt][0], sacc[nt][1]);
            __half2 h23 = __floats2half2_rn(sacc[nt][2], sacc[nt][3]);
            __half2 e01 = __floats2half2_rn(sacc[nt][0] - __low2float(h01),
                                            sacc[nt][1] - __high2float(h01));
            __half2 e23 = __floats2half2_rn(sacc[nt][2] - __low2float(h23),
                                            sacc[nt][3] - __high2float(h23));
            ph[nt][0] = h2_as_u32(h01);
            ph[nt][1] = h2_as_u32(h23);
            pl[nt][0] = h2_as_u32(e01);
            pl[nt][1] = h2_as_u32(e23);
        }

        const uint32_t vbase = kvb + 2 * KV_BYTES;
#pragma unroll
        for (int kk = 0; kk < 4; ++kk) {
            uint32_t pa[4]  = { ph[2 * kk][0], ph[2 * kk][1], ph[2 * kk + 1][0], ph[2 * kk + 1][1] };
            uint32_t pal[4] = { pl[2 * kk][0], pl[2 * kk][1], pl[2 * kk + 1][0], pl[2 * kk + 1][1] };
#pragma unroll
            for (int nt = 0; nt < 8; ++nt) {
                uint32_t va = vbase + ((kk * 16 + vRowP) * ASTR + nt * 16 + vColP) * 2;
                uint32_t vh[4], vl[4];
                ldsm_x4_t(vh, va);
                ldsm_x4_t(vl, va + KV_BYTES);
                mma_f16(oacc[2 * nt],     pa,  vh[0], vh[1]);
                mma_f16(oacc[2 * nt],     pa,  vl[0], vl[1]);
                mma_f16(oacc[2 * nt],     pal, vh[0], vh[1]);
                mma_f16(oacc[2 * nt + 1], pa,  vh[2], vh[3]);
                mma_f16(oacc[2 * nt + 1], pa,  vl[2], vl[3]);
                mma_f16(oacc[2 * nt + 1], pal, vh[2], vh[3]);
            }
        }
    }

    // ---- epilogue: normalize + split to fp16 hi/lo ----
    float inv0 = 1.0f / l0, inv1 = 1.0f / l1;
    const int trow = b * SEQ + row0g;
    const int cc = (lane & 3) * 2;
#pragma unroll
    for (int nt = 0; nt < 16; ++nt) {
        int col = h * HD + nt * 8 + cc;
        float o0 = oacc[nt][0] * inv0, o1 = oacc[nt][1] * inv0;
        float o2 = oacc[nt][2] * inv1, o3 = oacc[nt][3] * inv1;
        __half2 h01 = __floats2half2_rn(o0, o1);
        __half2 h23 = __floats2half2_rn(o2, o3);
        __half2 l01 = __floats2half2_rn(o0 - __low2float(h01), o1 - __high2float(h01));
        __half2 l23 = __floats2half2_rn(o2 - __low2float(h23), o3 - __high2float(h23));
        *reinterpret_cast<uint32_t*>(&Ohi[(size_t)trow * HID + col]) = h2_as_u32(h01);
        *reinterpret_cast<uint32_t*>(&Olo[(size_t)trow * HID + col]) = h2_as_u32(l01);
        *reinterpret_cast<uint32_t*>(&Ohi[(size_t)(trow + 8) * HID + col]) = h2_as_u32(h23);
        *reinterpret_cast<uint32_t*>(&Olo[(size_t)(trow + 8) * HID + col]) = h2_as_u32(l23);
    }
}

// ---------------------------------------------------------------------------
extern "C" void kernel_launch(void* const* d_in, const int* in_sizes, int n_in,
                              void* d_out, int out_size) {
    const float* hs    = (const float*)d_in[0];
    const float* w_qkv = (const float*)d_in[1];
    const float* w_o   = (const float*)d_in[2];
    float* out = (float*)d_out;

    float* qkv = nullptr;
    __half *hshi, *hslo, *wq, *wo, *atthi, *attlo;
    __half *qhi, *qlo, *khi, *klo, *vhi, *vlo;
    cudaGetSymbolAddress((void**)&qkv, g_qkv);
    cudaGetSymbolAddress((void**)&hshi, g_hshi);
    cudaGetSymbolAddress((void**)&hslo, g_hslo);
    cudaGetSymbolAddress((void**)&wq, g_wq);
    cudaGetSymbolAddress((void**)&wo, g_wo);
    cudaGetSymbolAddress((void**)&atthi, g_atthi);
    cudaGetSymbolAddress((void**)&attlo, g_attlo);
    cudaGetSymbolAddress((void**)&qhi, g_qhi);
    cudaGetSymbolAddress((void**)&qlo, g_qlo);
    cudaGetSymbolAddress((void**)&khi, g_khi);
    cudaGetSymbolAddress((void**)&klo, g_klo);
    cudaGetSymbolAddress((void**)&vhi, g_vhi);
    cudaGetSymbolAddress((void**)&vlo, g_vlo);

    cudaFuncSetAttribute(gemm_fp16x2, cudaFuncAttributeMaxDynamicSharedMemorySize, GEMM_SMEM);
    cudaFuncSetAttribute(attn_mma, cudaFuncAttributeMaxDynamicSharedMemorySize, ATT_SMEM);

    // 0) pre-convert: activations -> fp16 hi/lo; weights -> fp16 single
    split2h<<<(TT * HID / 8 + 255) / 256, 256>>>(hs, hshi, hslo, TT * HID / 8);
    convh<<<(QKVD * HID / 8 + 255) / 256, 256>>>(w_qkv, wq, QKVD * HID / 8);
    convh<<<(HID * HID / 8 + 255) / 256, 256>>>(w_o, wo, HID * HID / 8);

    // 1) QKV projection (fp16x2)
    {
        dim3 grid(QKVD / GBN, TT / GBM);
        gemm_fp16x2<<<grid, 256, GEMM_SMEM>>>(hshi, hslo, wq, qkv, TT, QKVD, HID);
    }
    // 2) fused RoPE + split to fp16 hi/lo (head-major)
    {
        int total = TT * (NH + 2 * NKV) * 64;
        rope_split<<<total / 256, 256>>>(qkv, qhi, qlo, khi, klo, vhi, vlo);
    }
    // 3) tensor-core causal GQA attention -> split fp16 output
    {
        dim3 grid(SEQ / AQ, NH, NB);
        attn_mma<<<grid, 256, ATT_SMEM>>>(qhi, qlo, khi, klo, vhi, vlo, atthi, attlo);
    }
    // 4) output projection (fp16x2)
    {
        dim3 grid(HID / GBN, TT / GBM);
        gemm_fp16x2<<<grid, 256, GEMM_SMEM>>>(atthi, attlo, wo, out, TT, HID, HID);
    }
}

// round 15
// speedup vs baseline: 1.1331x; 1.1331x over previous
#include <cuda_runtime.h>
#include <cuda_bf16.h>
#include <math.h>
#include <stdint.h>

#define TT    4096      // BATCH * SEQ tokens
#define HID   4096
#define NH    32
#define NKV   8
#define HD    128
#define QKVD  6144      // (32 + 16) * 128
#define SEQ   1024
#define NB    4

// pre-split bf16 operand buffers
__device__ __nv_bfloat16 g_hshi[(size_t)TT * HID];
__device__ __nv_bfloat16 g_hslo[(size_t)TT * HID];
__device__ __nv_bfloat16 g_wqhi[(size_t)QKVD * HID];
__device__ __nv_bfloat16 g_wqlo[(size_t)QKVD * HID];
__device__ __nv_bfloat16 g_wohi[(size_t)HID * HID];
__device__ __nv_bfloat16 g_wolo[(size_t)HID * HID];
__device__ __nv_bfloat16 g_atthi[(size_t)TT * HID];
__device__ __nv_bfloat16 g_attlo[(size_t)TT * HID];
// split bf16 q/k/v (head-major)
__device__ __nv_bfloat16 g_qhi[(size_t)NB * NH * SEQ * HD];
__device__ __nv_bfloat16 g_qlo[(size_t)NB * NH * SEQ * HD];
__device__ __nv_bfloat16 g_khi[(size_t)NB * NKV * SEQ * HD];
__device__ __nv_bfloat16 g_klo[(size_t)NB * NKV * SEQ * HD];
__device__ __nv_bfloat16 g_vhi[(size_t)NB * NKV * SEQ * HD];
__device__ __nv_bfloat16 g_vlo[(size_t)NB * NKV * SEQ * HD];

// ===========================================================================
// helpers
// ===========================================================================
__device__ __forceinline__ uint32_t smem_u32(const void* p) {
    uint32_t a;
    asm("{ .reg .u64 t; cvta.to.shared.u64 t, %1; cvt.u32.u64 %0, t; }"
        : "=r"(a) : "l"(p));
    return a;
}
__device__ __forceinline__ void ldsm_x4(uint32_t* r, uint32_t addr) {
    asm volatile("ldmatrix.sync.aligned.m8n8.x4.shared.b16 {%0,%1,%2,%3}, [%4];"
                 : "=r"(r[0]), "=r"(r[1]), "=r"(r[2]), "=r"(r[3]) : "r"(addr));
}
__device__ __forceinline__ void ldsm_x4_t(uint32_t* r, uint32_t addr) {
    asm volatile("ldmatrix.sync.aligned.m8n8.x4.trans.shared.b16 {%0,%1,%2,%3}, [%4];"
                 : "=r"(r[0]), "=r"(r[1]), "=r"(r[2]), "=r"(r[3]) : "r"(addr));
}
__device__ __forceinline__ void mma_bf16(float* c, const uint32_t* a,
                                         uint32_t b0, uint32_t b1) {
    asm volatile(
        "mma.sync.aligned.m16n8k16.row.col.f32.bf16.bf16.f32 "
        "{%0,%1,%2,%3}, {%4,%5,%6,%7}, {%8,%9}, {%0,%1,%2,%3};"
        : "+f"(c[0]), "+f"(c[1]), "+f"(c[2]), "+f"(c[3])
        : "r"(a[0]), "r"(a[1]), "r"(a[2]), "r"(a[3]), "r"(b0), "r"(b1));
}
__device__ __forceinline__ void cp16(uint32_t dst, const void* src) {
    asm volatile("cp.async.cg.shared.global [%0], [%1], 16;" :: "r"(dst), "l"(src));
}
#define CP_COMMIT() asm volatile("cp.async.commit_group;" ::: "memory")
#define CP_WAIT0()  asm volatile("cp.async.wait_group 0;" ::: "memory")
#define CP_WAIT1()  asm volatile("cp.async.wait_group 1;" ::: "memory")

// split 4 fp32 -> packed hi bf16x2 pair + lo bf16x2 pair
__device__ __forceinline__ void split4(float4 f, uint32_t* hi, uint32_t* lo) {
    uint32_t x0 = __float_as_uint(f.x), x1 = __float_as_uint(f.y);
    uint32_t x2 = __float_as_uint(f.z), x3 = __float_as_uint(f.w);
    hi[0] = __byte_perm(x0, x1, 0x7632);
    hi[1] = __byte_perm(x2, x3, 0x7632);
    float l0 = f.x - __uint_as_float(x0 & 0xFFFF0000u);
    float l1 = f.y - __uint_as_float(x1 & 0xFFFF0000u);
    float l2 = f.z - __uint_as_float(x2 & 0xFFFF0000u);
    float l3 = f.w - __uint_as_float(x3 & 0xFFFF0000u);
    __nv_bfloat162 b0 = __floats2bfloat162_rn(l0, l1);
    __nv_bfloat162 b1 = __floats2bfloat162_rn(l2, l3);
    lo[0] = *reinterpret_cast<uint32_t*>(&b0);
    lo[1] = *reinterpret_cast<uint32_t*>(&b1);
}

// ===========================================================================
// split2: fp32 buffer -> bf16 hi/lo buffers.  8 elements per thread.
// ===========================================================================
__global__ __launch_bounds__(256) void split2(const float* __restrict__ src,
                                              __nv_bfloat16* __restrict__ hi,
                                              __nv_bfloat16* __restrict__ lo,
                                              int n8) {
    int i = blockIdx.x * 256 + threadIdx.x;
    if (i >= n8) return;
    const float4* s = reinterpret_cast<const float4*>(src) + (size_t)i * 2;
    float4 f0 = s[0], f1 = s[1];
    uint32_t h0[2], l0[2], h1[2], l1[2];
    split4(f0, h0, l0);
    split4(f1, h1, l1);
    *reinterpret_cast<uint4*>(hi + (size_t)i * 8) = make_uint4(h0[0], h0[1], h1[0], h1[1]);
    *reinterpret_cast<uint4*>(lo + (size_t)i * 8) = make_uint4(l0[0], l0[1], l1[0], l1[1]);
}

// ===========================================================================
// GEMM core config (R12 best: bf16x3, product-major, 3-stage, reg dbuf)
// ===========================================================================
#define GBM 128
#define GBN 128
#define GKB 64
#define GSTR 72                        // element stride (144B row)
#define GTILEB (128 * GSTR * 2)        // 18432 B per tensor tile
#define GSTAGEB (4 * GTILEB)           // 73728 B per stage
#define GEMM_SMEM (3 * GSTAGEB)        // 221184 B

#define GEMM_MAINLOOP(Ahi, Alo, Bhi, Blo, K)                                      \
    const uint32_t aOffB = ((wm * 32 + (lane & 15)) * GSTR + (lane >> 4) * 8) * 2; \
    const uint32_t bOffB = ((wn * 64 + (lane & 7) + ((lane >> 4) & 1) * 8) * GSTR  \
                           + ((lane >> 3) & 1) * 8) * 2;                           \
    const int r0 = tid >> 3;                                                       \
    const int cc0 = tid & 7;                                                       \
    auto load_stage = [&](uint32_t base, int k0) {                                 \
        _Pragma("unroll")                                                          \
        for (int u = 0; u < 4; ++u) {                                              \
            int row = r0 + u * 32;                                                 \
            uint32_t d = base + row * (GSTR * 2) + cc0 * 16;                       \
            size_t ao = (size_t)(bm + row) * K + k0 + cc0 * 8;                     \
            size_t bo = (size_t)(bn + row) * K + k0 + cc0 * 8;                     \
            cp16(d, Ahi + ao);                                                     \
            cp16(d + GTILEB, Alo + ao);                                            \
            cp16(d + 2 * GTILEB, Bhi + bo);                                        \
            cp16(d + 3 * GTILEB, Blo + bo);                                        \
        }                                                                          \
    };                                                                             \
    const int NC = K / GKB;                                                        \
    load_stage(sb, 0);                                                             \
    CP_COMMIT();                                                                   \
    load_stage(sb + GSTAGEB, GKB);                                                 \
    CP_COMMIT();                                                                   \
    int scur = 0, snext = 2;                                                       \
    for (int kc = 0; kc < NC; ++kc) {                                              \
        if (kc == NC - 1) { CP_WAIT0(); } else { CP_WAIT1(); }                     \
        __syncthreads();                                                           \
        if (kc + 2 < NC) {                                                         \
            load_stage(sb + snext * GSTAGEB, (kc + 2) * GKB);                      \
            CP_COMMIT();                                                           \
        }                                                                          \
        const uint32_t base = sb + scur * GSTAGEB;                                 \
        scur = (scur == 2) ? 0 : scur + 1;                                         \
        snext = (snext == 2) ? 0 : snext + 1;                                      \
        uint32_t ah[2][2][4], al[2][2][4], bh[2][4][4], bl[2][4][4];               \
        _Pragma("unroll")                                                          \
        for (int mt = 0; mt < 2; ++mt) {                                           \
            uint32_t aa = base + aOffB + mt * (16 * GSTR * 2);                     \
            ldsm_x4(ah[0][mt], aa);                                                \
            ldsm_x4(al[0][mt], aa + GTILEB);                                       \
        }                                                                          \
        _Pragma("unroll")                                                          \
        for (int p = 0; p < 4; ++p) {                                              \
            uint32_t ba = base + 2 * GTILEB + bOffB + p * (16 * GSTR * 2);         \
            ldsm_x4(bh[0][p], ba);                                                 \
            ldsm_x4(bl[0][p], ba + GTILEB);                                        \
        }                                                                          \
        _Pragma("unroll")                                                          \
        for (int ks = 0; ks < 4; ++ks) {                                           \
            const int cur = ks & 1, nxt = cur ^ 1;                                 \
            if (ks < 3) {                                                          \
                const uint32_t ko = (ks + 1) * 32;                                 \
                _Pragma("unroll")                                                  \
                for (int mt = 0; mt < 2; ++mt) {                                   \
                    uint32_t aa = base + aOffB + mt * (16 * GSTR * 2) + ko;        \
                    ldsm_x4(ah[nxt][mt], aa);                                      \
                    ldsm_x4(al[nxt][mt], aa + GTILEB);                             \
                }                                                                  \
                _Pragma("unroll")                                                  \
                for (int p = 0; p < 4; ++p) {                                      \
                    uint32_t ba = base + 2 * GTILEB + bOffB                        \
                                  + p * (16 * GSTR * 2) + ko;                      \
                    ldsm_x4(bh[nxt][p], ba);                                       \
                    ldsm_x4(bl[nxt][p], ba + GTILEB);                              \
                }                                                                  \
            }                                                                      \
            _Pragma("unroll")                                                      \
            for (int prod = 0; prod < 3; ++prod) {                                 \
                _Pragma("unroll")                                                  \
                for (int p = 0; p < 4; ++p)                                        \
                    _Pragma("unroll")                                              \
                    for (int n2 = 0; n2 < 2; ++n2) {                               \
                        const int nt = p * 2 + n2;                                 \
                        uint32_t b0, b1;                                           \
                        if (prod == 1) {                                           \
                            b0 = bl[cur][p][n2 * 2]; b1 = bl[cur][p][n2 * 2 + 1];  \
                        } else {                                                   \
                            b0 = bh[cur][p][n2 * 2]; b1 = bh[cur][p][n2 * 2 + 1];  \
                        }                                                          \
                        _Pragma("unroll")                                          \
                        for (int mt = 0; mt < 2; ++mt) {                           \
                            const uint32_t* af =                                   \
                                (prod == 2) ? al[cur][mt] : ah[cur][mt];           \
                            mma_bf16(acc[mt][nt], af, b0, b1);                     \
                        }                                                          \
                    }                                                              \
            }                                                                      \
        }                                                                          \
    }

// ===========================================================================
// gemm_ps3: plain fp32-C epilogue — used for the O-projection.
// ===========================================================================
__global__ __launch_bounds__(256, 1) void gemm_ps3(
        const __nv_bfloat16* __restrict__ Ahi, const __nv_bfloat16* __restrict__ Alo,
        const __nv_bfloat16* __restrict__ Bhi, const __nv_bfloat16* __restrict__ Blo,
        float* __restrict__ C, int M, int N, int K) {
    extern __shared__ char sm8[];
    const uint32_t sb = smem_u32(sm8);
    const int tid = threadIdx.x;
    const int wid = tid >> 5;
    const int lane = tid & 31;
    const int wm = wid & 3;
    const int wn = wid >> 2;
    const int bm = blockIdx.y * GBM;
    const int bn = blockIdx.x * GBN;

    float acc[2][8][4];
#pragma unroll
    for (int i = 0; i < 2; i++)
#pragma unroll
        for (int j = 0; j < 8; j++)
#pragma unroll
            for (int q = 0; q < 4; q++) acc[i][j][q] = 0.f;

    GEMM_MAINLOOP(Ahi, Alo, Bhi, Blo, K)

    const int g = lane >> 2;
    const int cc = (lane & 3) * 2;
#pragma unroll
    for (int mt = 0; mt < 2; ++mt) {
        int rowc = bm + wm * 32 + mt * 16 + g;
#pragma unroll
        for (int nt = 0; nt < 8; ++nt) {
            int col = bn + wn * 64 + nt * 8 + cc;
            *reinterpret_cast<float2*>(&C[(size_t)rowc * N + col]) =
                make_float2(acc[mt][nt][0], acc[mt][nt][1]);
            *reinterpret_cast<float2*>(&C[(size_t)(rowc + 8) * N + col]) =
                make_float2(acc[mt][nt][2], acc[mt][nt][3]);
        }
    }
}

// ===========================================================================
// gemm_qkv: fused RoPE + head-major bf16 split epilogue (bn>>7 = head).
// ===========================================================================
__global__ __launch_bounds__(256, 1) void gemm_qkv(
        const __nv_bfloat16* __restrict__ Ahi, const __nv_bfloat16* __restrict__ Alo,
        const __nv_bfloat16* __restrict__ Bhi, const __nv_bfloat16* __restrict__ Blo,
        __nv_bfloat16* __restrict__ qhi, __nv_bfloat16* __restrict__ qlo,
        __nv_bfloat16* __restrict__ khi, __nv_bfloat16* __restrict__ klo,
        __nv_bfloat16* __restrict__ vhi, __nv_bfloat16* __restrict__ vlo,
        int K) {
    extern __shared__ char sm8[];
    const uint32_t sb = smem_u32(sm8);
    const int tid = threadIdx.x;
    const int wid = tid >> 5;
    const int lane = tid & 31;
    const int wm = wid & 3;
    const int wn = wid >> 2;
    const int bm = blockIdx.y * GBM;
    const int bn = blockIdx.x * GBN;

    float acc[2][8][4];
#pragma unroll
    for (int i = 0; i < 2; i++)
#pragma unroll
        for (int j = 0; j < 8; j++)
#pragma unroll
            for (int q = 0; q < 4; q++) acc[i][j][q] = 0.f;

    GEMM_MAINLOOP(Ahi, Alo, Bhi, Blo, K)

    // stage fp32 tile in smem [128][132]
    __syncthreads();
    float* cs = reinterpret_cast<float*>(sm8);
    const int g = lane >> 2;
    const int cc = (lane & 3) * 2;
#pragma unroll
    for (int mt = 0; mt < 2; ++mt) {
        int rowl = wm * 32 + mt * 16 + g;
#pragma unroll
        for (int nt = 0; nt < 8; ++nt) {
            int coll = wn * 64 + nt * 8 + cc;
            *reinterpret_cast<float2*>(&cs[rowl * 132 + coll]) =
                make_float2(acc[mt][nt][0], acc[mt][nt][1]);
            *reinterpret_cast<float2*>(&cs[(rowl + 8) * 132 + coll]) =
                make_float2(acc[mt][nt][2], acc[mt][nt][3]);
        }
    }
    __syncthreads();

    // RoPE + truncation-split + head-major scatter
    const int hh = bn >> 7;                  // packed head 0..47
    __nv_bfloat16 *dh, *dl;
    if (hh < NH)            { dh = qhi; dl = qlo; }
    else if (hh < NH + NKV) { dh = khi; dl = klo; }
    else                    { dh = vhi; dl = vlo; }
    const bool do_rope = (hh < NH + NKV);
    const bool do_scale = (hh < NH);

#pragma unroll 4
    for (int it = 0; it < 32; ++it) {
        int p = it * 256 + tid;
        int row = p >> 6;
        int i = p & 63;
        float x1 = cs[row * 132 + i];
        float x2 = cs[row * 132 + i + 64];
        int t = bm + row;
        int s = t & (SEQ - 1);
        int b = t >> 10;
        float y1, y2;
        if (do_rope) {
            const float L2T = 13.287712379549449f;   // log2(10000)
            float invf = exp2f(-(float)(2 * i) * (1.0f / (float)HD) * L2T);
            float ang = (float)s * invf;
            float sn, csv;
            sincosf(ang, &sn, &csv);
            y1 = x1 * csv - x2 * sn;
            y2 = x2 * csv + x1 * sn;
        } else { y1 = x1; y2 = x2; }
        if (do_scale) {
            const float sc = 0.08838834764831845f;   // 128^-0.5
            y1 *= sc; y2 *= sc;
        }
        size_t off;
        if (hh < NH)            off = ((size_t)(b * NH + hh) * SEQ + s) * HD;
        else if (hh < NH + NKV) off = ((size_t)(b * NKV + (hh - NH)) * SEQ + s) * HD;
        else                    off = ((size_t)(b * NKV + (hh - NH - NKV)) * SEQ + s) * HD;
        uint32_t u1 = __float_as_uint(y1), u2 = __float_as_uint(y2);
        float h1 = __uint_as_float(u1 & 0xFFFF0000u);
        float h2 = __uint_as_float(u2 & 0xFFFF0000u);
        dh[off + i]      = __float2bfloat16(h1);
        dh[off + i + 64] = __float2bfloat16(h2);
        dl[off + i]      = __float2bfloat16(y1 - h1);
        dl[off + i + 64] = __float2bfloat16(y2 - h2);
    }
}

// ===========================================================================
// Tensor-core causal GQA flash attention (bf16x3 split) — unchanged R12.
// ===========================================================================
#define AQ   128
#define AKT  64
#define ASTR 136
#define Q_BYTES   (AQ * ASTR * 2)
#define KV_BYTES  (AKT * ASTR * 2)
#define KVBUF     (4 * KV_BYTES)
#define ATT_SMEM  (2 * Q_BYTES + 2 * KVBUF)

__global__ __launch_bounds__(256) void attn_mma(
        const __nv_bfloat16* __restrict__ Qhi, const __nv_bfloat16* __restrict__ Qlo,
        const __nv_bfloat16* __restrict__ Khi, const __nv_bfloat16* __restrict__ Klo,
        const __nv_bfloat16* __restrict__ Vhi, const __nv_bfloat16* __restrict__ Vlo,
        __nv_bfloat16* __restrict__ Ohi, __nv_bfloat16* __restrict__ Olo) {
    extern __shared__ char sm8[];
    const uint32_t sb = smem_u32(sm8);
    const int tid = threadIdx.x, wid = tid >> 5, lane = tid & 31;
    const int qtile = gridDim.x - 1 - blockIdx.x;
    const int h = blockIdx.y, b = blockIdx.z;
    const int kvh = h >> 2;

    const size_t qbase = ((size_t)(b * NH + h) * SEQ + qtile * AQ) * HD;
    const size_t kbase = ((size_t)(b * NKV + kvh) * SEQ) * HD;

    for (int i = tid; i < AQ * 16; i += 256) {
        int row = i >> 4, c = i & 15;
        uint32_t d = sb + row * (ASTR * 2) + c * 16;
        const size_t src = qbase + (size_t)row * HD + c * 8;
        cp16(d, Qhi + src);
        cp16(d + Q_BYTES, Qlo + src);
    }
    {
        uint32_t dst0 = sb + 2 * Q_BYTES;
        for (int i = tid; i < AKT * 16; i += 256) {
            int row = i >> 4, c = i & 15;
            uint32_t d = dst0 + row * (ASTR * 2) + c * 16;
            const size_t src = kbase + (size_t)row * HD + c * 8;
            cp16(d,                Khi + src);
            cp16(d + KV_BYTES,     Klo + src);
            cp16(d + 2 * KV_BYTES, Vhi + src);
            cp16(d + 3 * KV_BYTES, Vlo + src);
        }
    }
    CP_COMMIT();

    float oacc[16][4];
#pragma unroll
    for (int n = 0; n < 16; n++)
#pragma unroll
        for (int q = 0; q < 4; q++) oacc[n][q] = 0.f;
    float m0 = -1e30f, m1 = -1e30f, l0 = 0.f, l1 = 0.f;

    const uint32_t aRow = wid * 16 + (lane & 15);
    const uint32_t aColP = (lane >> 4) * 8;
    const uint32_t qAddr = sb + (aRow * ASTR + aColP) * 2;
    const uint32_t bRowP = (lane & 7) + ((lane >> 4) & 1) * 8;
    const uint32_t bColP = ((lane >> 3) & 1) * 8;
    const uint32_t vRowP = (lane & 7) + ((lane >> 3) & 1) * 8;
    const uint32_t vColP = (lane >> 4) * 8;

    const int nkt = 2 * qtile + 2;
    const int row0g = qtile * AQ + wid * 16 + (lane >> 2);

    for (int kt = 0; kt < nkt; ++kt) {
        const int s = kt & 1;
        CP_WAIT0();
        __syncthreads();
        if (kt + 1 < nkt) {
            uint32_t dst0 = sb + 2 * Q_BYTES + (s ^ 1) * KVBUF;
            const size_t kvoff = kbase + (size_t)(kt + 1) * AKT * HD;
            for (int i = tid; i < AKT * 16; i += 256) {
                int row = i >> 4, c = i & 15;
                uint32_t d = dst0 + row * (ASTR * 2) + c * 16;
                const size_t src = kvoff + (size_t)row * HD + c * 8;
                cp16(d,                Khi + src);
                cp16(d + KV_BYTES,     Klo + src);
                cp16(d + 2 * KV_BYTES, Vhi + src);
                cp16(d + 3 * KV_BYTES, Vlo + src);
            }
            CP_COMMIT();
        }

        const uint32_t kvb = sb + 2 * Q_BYTES + s * KVBUF;

        float sacc[8][4];
#pragma unroll
        for (int n = 0; n < 8; n++)
#pragma unroll
            for (int q = 0; q < 4; q++) sacc[n][q] = 0.f;

#pragma unroll
        for (int ks = 0; ks < 8; ++ks) {
            uint32_t aq[4], aql[4];
            uint32_t qa = qAddr + ks * 32;
            ldsm_x4(aq, qa);
            ldsm_x4(aql, qa + Q_BYTES);
            uint32_t bh[4][4], bl[4][4];
#pragma unroll
            for (int p = 0; p < 4; ++p) {
                uint32_t ba = kvb + ((p * 16 + bRowP) * ASTR + ks * 16 + bColP) * 2;
                ldsm_x4(bh[p], ba);
                ldsm_x4(bl[p], ba + KV_BYTES);
            }
#pragma unroll
            for (int nt = 0; nt < 8; ++nt) {
                uint32_t h0 = bh[nt >> 1][(nt & 1) * 2];
                uint32_t h1 = bh[nt >> 1][(nt & 1) * 2 + 1];
                uint32_t q0 = bl[nt >> 1][(nt & 1) * 2];
                uint32_t q1 = bl[nt >> 1][(nt & 1) * 2 + 1];
                mma_bf16(sacc[nt], aq, h0, h1);
                mma_bf16(sacc[nt], aq, q0, q1);
                mma_bf16(sacc[nt], aql, h0, h1);
            }
        }

        if (kt * AKT + AKT - 1 > qtile * AQ + wid * 16) {
            const int colb = kt * AKT + (lane & 3) * 2;
#pragma unroll
            for (int nt = 0; nt < 8; ++nt) {
                int c0 = colb + nt * 8;
                if (c0 > row0g)         sacc[nt][0] = -1e30f;
                if (c0 + 1 > row0g)     sacc[nt][1] = -1e30f;
                if (c0 > row0g + 8)     sacc[nt][2] = -1e30f;
                if (c0 + 1 > row0g + 8) sacc[nt][3] = -1e30f;
            }
        }

        float mx0 = -1e30f, mx1 = -1e30f;
#pragma unroll
        for (int nt = 0; nt < 8; ++nt) {
            mx0 = fmaxf(mx0, fmaxf(sacc[nt][0], sacc[nt][1]));
            mx1 = fmaxf(mx1, fmaxf(sacc[nt][2], sacc[nt][3]));
        }
        mx0 = fmaxf(mx0, __shfl_xor_sync(0xffffffffu, mx0, 1));
        mx0 = fmaxf(mx0, __shfl_xor_sync(0xffffffffu, mx0, 2));
        mx1 = fmaxf(mx1, __shfl_xor_sync(0xffffffffu, mx1, 1));
        mx1 = fmaxf(mx1, __shfl_xor_sync(0xffffffffu, mx1, 2));
        float nm0 = fmaxf(m0, mx0), nm1 = fmaxf(m1, mx1);
        float r0 = 0.f, r1 = 0.f;
#pragma unroll
        for (int nt = 0; nt < 8; ++nt) {
            sacc[nt][0] = __expf(sacc[nt][0] - nm0);
            sacc[nt][1] = __expf(sacc[nt][1] - nm0);
            sacc[nt][2] = __expf(sacc[nt][2] - nm1);
            sacc[nt][3] = __expf(sacc[nt][3] - nm1);
            r0 += sacc[nt][0] + sacc[nt][1];
            r1 += sacc[nt][2] + sacc[nt][3];
        }
        r0 += __shfl_xor_sync(0xffffffffu, r0, 1);
        r0 += __shfl_xor_sync(0xffffffffu, r0, 2);
        r1 += __shfl_xor_sync(0xffffffffu, r1, 1);
        r1 += __shfl_xor_sync(0xffffffffu, r1, 2);
        float a0 = __expf(m0 - nm0), a1 = __expf(m1 - nm1);
        l0 = l0 * a0 + r0;
        l1 = l1 * a1 + r1;
        m0 = nm0; m1 = nm1;
#pragma unroll
        for (int n = 0; n < 16; ++n) {
            oacc[n][0] *= a0; oacc[n][1] *= a0;
            oacc[n][2] *= a1; oacc[n][3] *= a1;
        }

        uint32_t ph[8][2], pl[8][2];
#pragma unroll
        for (int nt = 0; nt < 8; ++nt) {
            uint32_t u0 = __float_as_uint(sacc[nt][0]);
            uint32_t u1 = __float_as_uint(sacc[nt][1]);
            uint32_t u2 = __float_as_uint(sacc[nt][2]);
            uint32_t u3 = __float_as_uint(sacc[nt][3]);
            ph[nt][0] = __byte_perm(u0, u1, 0x7632);
            ph[nt][1] = __byte_perm(u2, u3, 0x7632);
            float e0 = sacc[nt][0] - __uint_as_float(u0 & 0xFFFF0000u);
            float e1 = sacc[nt][1] - __uint_as_float(u1 & 0xFFFF0000u);
            float e2 = sacc[nt][2] - __uint_as_float(u2 & 0xFFFF0000u);
            float e3 = sacc[nt][3] - __uint_as_float(u3 & 0xFFFF0000u);
            __nv_bfloat162 p01 = __floats2bfloat162_rn(e0, e1);
            __nv_bfloat162 p23 = __floats2bfloat162_rn(e2, e3);
            pl[nt][0] = *reinterpret_cast<uint32_t*>(&p01);
            pl[nt][1] = *reinterpret_cast<uint32_t*>(&p23);
        }

        const uint32_t vbase = kvb + 2 * KV_BYTES;
#pragma unroll
        for (int kk = 0; kk < 4; ++kk) {
            uint32_t pa[4]  = { ph[2 * kk][0], ph[2 * kk][1], ph[2 * kk + 1][0], ph[2 * kk + 1][1] };
            uint32_t pal[4] = { pl[2 * kk][0], pl[2 * kk][1], pl[2 * kk + 1][0], pl[2 * kk + 1][1] };
#pragma unroll
            for (int nt = 0; nt < 8; ++nt) {
                uint32_t va = vbase + ((kk * 16 + vRowP) * ASTR + nt * 16 + vColP) * 2;
                uint32_t vh[4], vl[4];
                ldsm_x4_t(vh, va);
                ldsm_x4_t(vl, va + KV_BYTES);
                mma_bf16(oacc[2 * nt],     pa,  vh[0], vh[1]);
                mma_bf16(oacc[2 * nt],     pa,  vl[0], vl[1]);
                mma_bf16(oacc[2 * nt],     pal, vh[0], vh[1]);
                mma_bf16(oacc[2 * nt + 1], pa,  vh[2], vh[3]);
                mma_bf16(oacc[2 * nt + 1], pa,  vl[2], vl[3]);
                mma_bf16(oacc[2 * nt + 1], pal, vh[2], vh[3]);
            }
        }
    }

    float inv0 = 1.0f / l0, inv1 = 1.0f / l1;
    const int trow = b * SEQ + row0g;
    const int cc = (lane & 3) * 2;
#pragma unroll
    for (int nt = 0; nt < 16; ++nt) {
        int col = h * HD + nt * 8 + cc;
        float o0 = oacc[nt][0] * inv0, o1 = oacc[nt][1] * inv0;
        float o2 = oacc[nt][2] * inv1, o3 = oacc[nt][3] * inv1;
        uint32_t u0 = __float_as_uint(o0), u1 = __float_as_uint(o1);
        uint32_t u2 = __float_as_uint(o2), u3 = __float_as_uint(o3);
        uint32_t hi01 = __byte_perm(u0, u1, 0x7632);
        uint32_t hi23 = __byte_perm(u2, u3, 0x7632);
        __nv_bfloat162 lo01 = __floats2bfloat162_rn(
            o0 - __uint_as_float(u0 & 0xFFFF0000u), o1 - __uint_as_float(u1 & 0xFFFF0000u));
        __nv_bfloat162 lo23 = __floats2bfloat162_rn(
            o2 - __uint_as_float(u2 & 0xFFFF0000u), o3 - __uint_as_float(u3 & 0xFFFF0000u));
        *reinterpret_cast<uint32_t*>(&Ohi[(size_t)trow * HID + col]) = hi01;
        *reinterpret_cast<uint32_t*>(&Olo[(size_t)trow * HID + col]) =
            *reinterpret_cast<uint32_t*>(&lo01);
        *reinterpret_cast<uint32_t*>(&Ohi[(size_t)(trow + 8) * HID + col]) = hi23;
        *reinterpret_cast<uint32_t*>(&Olo[(size_t)(trow + 8) * HID + col]) =
            *reinterpret_cast<uint32_t*>(&lo23);
    }
}

// ---------------------------------------------------------------------------
extern "C" void kernel_launch(void* const* d_in, const int* in_sizes, int n_in,
                              void* d_out, int out_size) {
    const float* hs    = (const float*)d_in[0];
    const float* w_qkv = (const float*)d_in[1];
    const float* w_o   = (const float*)d_in[2];
    float* out = (float*)d_out;

    __nv_bfloat16 *hshi, *hslo, *wqhi, *wqlo, *wohi, *wolo, *atthi, *attlo;
    __nv_bfloat16 *qhi, *qlo, *khi, *klo, *vhi, *vlo;
    cudaGetSymbolAddress((void**)&hshi, g_hshi);
    cudaGetSymbolAddress((void**)&hslo, g_hslo);
    cudaGetSymbolAddress((void**)&wqhi, g_wqhi);
    cudaGetSymbolAddress((void**)&wqlo, g_wqlo);
    cudaGetSymbolAddress((void**)&wohi, g_wohi);
    cudaGetSymbolAddress((void**)&wolo, g_wolo);
    cudaGetSymbolAddress((void**)&atthi, g_atthi);
    cudaGetSymbolAddress((void**)&attlo, g_attlo);
    cudaGetSymbolAddress((void**)&qhi, g_qhi);
    cudaGetSymbolAddress((void**)&qlo, g_qlo);
    cudaGetSymbolAddress((void**)&khi, g_khi);
    cudaGetSymbolAddress((void**)&klo, g_klo);
    cudaGetSymbolAddress((void**)&vhi, g_vhi);
    cudaGetSymbolAddress((void**)&vlo, g_vlo);

    cudaFuncSetAttribute(gemm_ps3, cudaFuncAttributeMaxDynamicSharedMemorySize, GEMM_SMEM);
    cudaFuncSetAttribute(gemm_qkv, cudaFuncAttributeMaxDynamicSharedMemorySize, GEMM_SMEM);
    cudaFuncSetAttribute(attn_mma, cudaFuncAttributeMaxDynamicSharedMemorySize, ATT_SMEM);

    // 0) pre-split inputs and weights to bf16 hi/lo
    split2<<<(TT * HID / 8 + 255) / 256, 256>>>(hs, hshi, hslo, TT * HID / 8);
    split2<<<(QKVD * HID / 8 + 255) / 256, 256>>>(w_qkv, wqhi, wqlo, QKVD * HID / 8);
    split2<<<(HID * HID / 8 + 255) / 256, 256>>>(w_o, wohi, wolo, HID * HID / 8);

    // 1) QKV projection with fused RoPE + head-major split epilogue
    {
        dim3 grid(QKVD / GBN, TT / GBM);
        gemm_qkv<<<grid, 256, GEMM_SMEM>>>(hshi, hslo, wqhi, wqlo,
                                           qhi, qlo, khi, klo, vhi, vlo, HID);
    }
    // 2) tensor-core causal GQA attention -> split bf16 output
    {
        dim3 grid(SEQ / AQ, NH, NB);
        attn_mma<<<grid, 256, ATT_SMEM>>>(qhi, qlo, khi, klo, vhi, vlo, atthi, attlo);
    }
    // 3) output projection
    {
        dim3 grid(HID / GBN, TT / GBM);
        gemm_ps3<<<grid, 256, GEMM_SMEM>>>(atthi, attlo, wohi, wolo, out, TT, HID, HID);
    }
}

// round 16
// speedup vs baseline: 1.4594x; 1.2879x over previous
#include <cuda_runtime.h>
#include <cuda_bf16.h>
#include <math.h>
#include <stdint.h>

#define TT    4096      // BATCH * SEQ tokens
#define HID   4096
#define NH    32
#define NKV   8
#define HD    128
#define QKVD  6144      // (32 + 16) * 128
#define SEQ   1024
#define NB    4

// tf32-rounded fp32 operand buffers
__device__ float g_hstf[(size_t)TT * HID];
__device__ float g_wqtf[(size_t)QKVD * HID];
__device__ float g_wotf[(size_t)HID * HID];
__device__ float g_atttf[(size_t)TT * HID];
// split bf16 q/k/v (head-major) for attention
__device__ __nv_bfloat16 g_qhi[(size_t)NB * NH * SEQ * HD];
__device__ __nv_bfloat16 g_qlo[(size_t)NB * NH * SEQ * HD];
__device__ __nv_bfloat16 g_khi[(size_t)NB * NKV * SEQ * HD];
__device__ __nv_bfloat16 g_klo[(size_t)NB * NKV * SEQ * HD];
__device__ __nv_bfloat16 g_vhi[(size_t)NB * NKV * SEQ * HD];
__device__ __nv_bfloat16 g_vlo[(size_t)NB * NKV * SEQ * HD];

// ===========================================================================
// helpers
// ===========================================================================
__device__ __forceinline__ uint32_t smem_u32(const void* p) {
    uint32_t a;
    asm("{ .reg .u64 t; cvta.to.shared.u64 t, %1; cvt.u32.u64 %0, t; }"
        : "=r"(a) : "l"(p));
    return a;
}
__device__ __forceinline__ void ldsm_x4(uint32_t* r, uint32_t addr) {
    asm volatile("ldmatrix.sync.aligned.m8n8.x4.shared.b16 {%0,%1,%2,%3}, [%4];"
                 : "=r"(r[0]), "=r"(r[1]), "=r"(r[2]), "=r"(r[3]) : "r"(addr));
}
__device__ __forceinline__ void ldsm_x4_t(uint32_t* r, uint32_t addr) {
    asm volatile("ldmatrix.sync.aligned.m8n8.x4.trans.shared.b16 {%0,%1,%2,%3}, [%4];"
                 : "=r"(r[0]), "=r"(r[1]), "=r"(r[2]), "=r"(r[3]) : "r"(addr));
}
__device__ __forceinline__ void mma_bf16(float* c, const uint32_t* a,
                                         uint32_t b0, uint32_t b1) {
    asm volatile(
        "mma.sync.aligned.m16n8k16.row.col.f32.bf16.bf16.f32 "
        "{%0,%1,%2,%3}, {%4,%5,%6,%7}, {%8,%9}, {%0,%1,%2,%3};"
        : "+f"(c[0]), "+f"(c[1]), "+f"(c[2]), "+f"(c[3])
        : "r"(a[0]), "r"(a[1]), "r"(a[2]), "r"(a[3]), "r"(b0), "r"(b1));
}
__device__ __forceinline__ void mma_tf32(float* c, const uint32_t* a,
                                         uint32_t b0, uint32_t b1) {
    asm volatile(
        "mma.sync.aligned.m16n8k8.row.col.f32.tf32.tf32.f32 "
        "{%0,%1,%2,%3}, {%4,%5,%6,%7}, {%8,%9}, {%0,%1,%2,%3};"
        : "+f"(c[0]), "+f"(c[1]), "+f"(c[2]), "+f"(c[3])
        : "r"(a[0]), "r"(a[1]), "r"(a[2]), "r"(a[3]), "r"(b0), "r"(b1));
}
__device__ __forceinline__ void cp16(uint32_t dst, const void* src) {
    asm volatile("cp.async.cg.shared.global [%0], [%1], 16;" :: "r"(dst), "l"(src));
}
#define CP_COMMIT() asm volatile("cp.async.commit_group;" ::: "memory")
#define CP_WAIT0()  asm volatile("cp.async.wait_group 0;" ::: "memory")
#define CP_WAIT1()  asm volatile("cp.async.wait_group 1;" ::: "memory")

__device__ __forceinline__ uint32_t f2tf32(float f) {
    uint32_t r;
    asm("cvt.rna.tf32.f32 %0, %1;" : "=r"(r) : "f"(f));
    return r;
}

// ===========================================================================
// conv_tf32: fp32 -> tf32-rounded fp32 (rna).  4 elements per thread.
// ===========================================================================
__global__ __launch_bounds__(256) void conv_tf32(const float* __restrict__ src,
                                                 float* __restrict__ dst, int n4) {
    int i = blockIdx.x * 256 + threadIdx.x;
    if (i >= n4) return;
    float4 f = reinterpret_cast<const float4*>(src)[i];
    uint4 o;
    o.x = f2tf32(f.x);
    o.y = f2tf32(f.y);
    o.z = f2tf32(f.z);
    o.w = f2tf32(f.w);
    reinterpret_cast<uint4*>(dst)[i] = o;
}

// ===========================================================================
// tf32 single-pass GEMM core (NT): C[M,N] = A[M,K] @ B[N,K]^T.
// CTA 128x128, BK=32, 256 threads (8 warps, 4Mx2N), warp tile 32x64.
// 2-stage cp.async, occ 2.  Fragments via scalar LDS (conflict-free, str 36).
// ===========================================================================
#define TBM 128
#define TBN 128
#define TBK 32
#define TSTR 36                         // float stride (144 B row)
#define TTILEB (128 * TSTR * 4)         // 18432 B
#define TSTAGEB (2 * TTILEB)            // 36864 B (A | B)
#define TGEMM_SMEM (2 * TSTAGEB)        // 73728 B

#define TF32_MAINLOOP(Ap, Bp, K)                                                  \
    const int r0 = tid >> 3;                                                       \
    const int cc0 = tid & 7;                                                       \
    auto load_stage = [&](uint32_t base, int k0) {                                 \
        _Pragma("unroll")                                                          \
        for (int u = 0; u < 4; ++u) {                                              \
            int row = r0 + u * 32;                                                 \
            uint32_t d = base + row * (TSTR * 4) + cc0 * 16;                       \
            cp16(d, Ap + (size_t)(bm + row) * K + k0 + cc0 * 4);                   \
            cp16(d + TTILEB, Bp + (size_t)(bn + row) * K + k0 + cc0 * 4);          \
        }                                                                          \
    };                                                                             \
    const int NC = K / TBK;                                                        \
    load_stage(sb, 0);                                                             \
    CP_COMMIT();                                                                   \
    const uint32_t aBase0 = sb + (wm * 32 + (lane >> 2)) * (TSTR * 4)              \
                            + (lane & 3) * 4;                                      \
    const uint32_t bBase0 = sb + TTILEB + (wn * 64 + (lane >> 2)) * (TSTR * 4)     \
                            + (lane & 3) * 4;                                      \
    for (int kc = 0; kc < NC; ++kc) {                                              \
        if (kc + 1 < NC) {                                                         \
            load_stage(sb + ((kc + 1) & 1) * TSTAGEB, (kc + 1) * TBK);             \
            CP_COMMIT();                                                           \
            CP_WAIT1();                                                            \
        } else {                                                                   \
            CP_WAIT0();                                                            \
        }                                                                          \
        __syncthreads();                                                           \
        const uint32_t soff = (kc & 1) * TSTAGEB;                                  \
        _Pragma("unroll")                                                          \
        for (int k8 = 0; k8 < 4; ++k8) {                                           \
            const uint32_t ko = k8 * 32;  /* 8 floats */                           \
            uint32_t a[2][4];                                                      \
            _Pragma("unroll")                                                      \
            for (int mt = 0; mt < 2; ++mt) {                                       \
                uint32_t ab = aBase0 + soff + mt * (16 * TSTR * 4) + ko;           \
                asm volatile("ld.shared.b32 %0, [%1];" : "=r"(a[mt][0]) : "r"(ab));\
                asm volatile("ld.shared.b32 %0, [%1];" : "=r"(a[mt][1])            \
                             : "r"(ab + 8 * TSTR * 4));                            \
                asm volatile("ld.shared.b32 %0, [%1];" : "=r"(a[mt][2])            \
                             : "r"(ab + 16));                                      \
                asm volatile("ld.shared.b32 %0, [%1];" : "=r"(a[mt][3])            \
                             : "r"(ab + 8 * TSTR * 4 + 16));                       \
            }                                                                      \
            _Pragma("unroll")                                                      \
            for (int nt = 0; nt < 8; ++nt) {                                       \
                uint32_t bb = bBase0 + soff + nt * (8 * TSTR * 4) + ko;            \
                uint32_t b0, b1;                                                   \
                asm volatile("ld.shared.b32 %0, [%1];" : "=r"(b0) : "r"(bb));      \
                asm volatile("ld.shared.b32 %0, [%1];" : "=r"(b1) : "r"(bb + 16)); \
                mma_tf32(acc[0][nt], a[0], b0, b1);                                \
                mma_tf32(acc[1][nt], a[1], b0, b1);                                \
            }                                                                      \
        }                                                                          \
        __syncthreads();                                                           \
    }

// plain fp32-C epilogue — used for the O-projection
__global__ __launch_bounds__(256, 2) void gemm_tf32(
        const float* __restrict__ A, const float* __restrict__ B,
        float* __restrict__ C, int M, int N, int K) {
    extern __shared__ char sm8[];
    const uint32_t sb = smem_u32(sm8);
    const int tid = threadIdx.x;
    const int wid = tid >> 5;
    const int lane = tid & 31;
    const int wm = wid & 3;
    const int wn = wid >> 2;
    const int bm = blockIdx.y * TBM;
    const int bn = blockIdx.x * TBN;

    float acc[2][8][4];
#pragma unroll
    for (int i = 0; i < 2; i++)
#pragma unroll
        for (int j = 0; j < 8; j++)
#pragma unroll
            for (int q = 0; q < 4; q++) acc[i][j][q] = 0.f;

    TF32_MAINLOOP(A, B, K)

    const int g = lane >> 2;
    const int cc = (lane & 3) * 2;
#pragma unroll
    for (int mt = 0; mt < 2; ++mt) {
        int rowc = bm + wm * 32 + mt * 16 + g;
#pragma unroll
        for (int nt = 0; nt < 8; ++nt) {
            int col = bn + wn * 64 + nt * 8 + cc;
            *reinterpret_cast<float2*>(&C[(size_t)rowc * N + col]) =
                make_float2(acc[mt][nt][0], acc[mt][nt][1]);
            *reinterpret_cast<float2*>(&C[(size_t)(rowc + 8) * N + col]) =
                make_float2(acc[mt][nt][2], acc[mt][nt][3]);
        }
    }
}

// QKV variant: fused RoPE + head-major bf16 hi/lo split epilogue (bn>>7 = head)
__global__ __launch_bounds__(256, 2) void gemm_qkv_tf32(
        const float* __restrict__ A, const float* __restrict__ B,
        __nv_bfloat16* __restrict__ qhi, __nv_bfloat16* __restrict__ qlo,
        __nv_bfloat16* __restrict__ khi, __nv_bfloat16* __restrict__ klo,
        __nv_bfloat16* __restrict__ vhi, __nv_bfloat16* __restrict__ vlo,
        int K) {
    extern __shared__ char sm8[];
    const uint32_t sb = smem_u32(sm8);
    const int tid = threadIdx.x;
    const int wid = tid >> 5;
    const int lane = tid & 31;
    const int wm = wid & 3;
    const int wn = wid >> 2;
    const int bm = blockIdx.y * TBM;
    const int bn = blockIdx.x * TBN;

    float acc[2][8][4];
#pragma unroll
    for (int i = 0; i < 2; i++)
#pragma unroll
        for (int j = 0; j < 8; j++)
#pragma unroll
            for (int q = 0; q < 4; q++) acc[i][j][q] = 0.f;

    TF32_MAINLOOP(A, B, K)

    // stage fp32 tile in smem [128][132]  (67584 B <= 73728 B)
    __syncthreads();
    float* cs = reinterpret_cast<float*>(sm8);
    const int g = lane >> 2;
    const int cc = (lane & 3) * 2;
#pragma unroll
    for (int mt = 0; mt < 2; ++mt) {
        int rowl = wm * 32 + mt * 16 + g;
#pragma unroll
        for (int nt = 0; nt < 8; ++nt) {
            int coll = wn * 64 + nt * 8 + cc;
            *reinterpret_cast<float2*>(&cs[rowl * 132 + coll]) =
                make_float2(acc[mt][nt][0], acc[mt][nt][1]);
            *reinterpret_cast<float2*>(&cs[(rowl + 8) * 132 + coll]) =
                make_float2(acc[mt][nt][2], acc[mt][nt][3]);
        }
    }
    __syncthreads();

    const int hh = bn >> 7;                  // packed head 0..47
    __nv_bfloat16 *dh, *dl;
    if (hh < NH)            { dh = qhi; dl = qlo; }
    else if (hh < NH + NKV) { dh = khi; dl = klo; }
    else                    { dh = vhi; dl = vlo; }
    const bool do_rope = (hh < NH + NKV);
    const bool do_scale = (hh < NH);

#pragma unroll 4
    for (int it = 0; it < 32; ++it) {
        int p = it * 256 + tid;
        int row = p >> 6;
        int i = p & 63;
        float x1 = cs[row * 132 + i];
        float x2 = cs[row * 132 + i + 64];
        int t = bm + row;
        int s = t & (SEQ - 1);
        int b = t >> 10;
        float y1, y2;
        if (do_rope) {
            const float L2T = 13.287712379549449f;   // log2(10000)
            float invf = exp2f(-(float)(2 * i) * (1.0f / (float)HD) * L2T);
            float ang = (float)s * invf;
            float sn, csv;
            sincosf(ang, &sn, &csv);
            y1 = x1 * csv - x2 * sn;
            y2 = x2 * csv + x1 * sn;
        } else { y1 = x1; y2 = x2; }
        if (do_scale) {
            const float sc = 0.08838834764831845f;   // 128^-0.5
            y1 *= sc; y2 *= sc;
        }
        size_t off;
        if (hh < NH)            off = ((size_t)(b * NH + hh) * SEQ + s) * HD;
        else if (hh < NH + NKV) off = ((size_t)(b * NKV + (hh - NH)) * SEQ + s) * HD;
        else                    off = ((size_t)(b * NKV + (hh - NH - NKV)) * SEQ + s) * HD;
        uint32_t u1 = __float_as_uint(y1), u2 = __float_as_uint(y2);
        float h1 = __uint_as_float(u1 & 0xFFFF0000u);
        float h2 = __uint_as_float(u2 & 0xFFFF0000u);
        dh[off + i]      = __float2bfloat16(h1);
        dh[off + i + 64] = __float2bfloat16(h2);
        dl[off + i]      = __float2bfloat16(y1 - h1);
        dl[off + i + 64] = __float2bfloat16(y2 - h2);
    }
}

// ===========================================================================
// Tensor-core causal GQA flash attention (bf16x3 split).
// Epilogue writes tf32-rounded fp32 (feeds O-proj A side).
// ===========================================================================
#define AQ   128
#define AKT  64
#define ASTR 136
#define Q_BYTES   (AQ * ASTR * 2)
#define KV_BYTES  (AKT * ASTR * 2)
#define KVBUF     (4 * KV_BYTES)
#define ATT_SMEM  (2 * Q_BYTES + 2 * KVBUF)

__global__ __launch_bounds__(256) void attn_mma(
        const __nv_bfloat16* __restrict__ Qhi, const __nv_bfloat16* __restrict__ Qlo,
        const __nv_bfloat16* __restrict__ Khi, const __nv_bfloat16* __restrict__ Klo,
        const __nv_bfloat16* __restrict__ Vhi, const __nv_bfloat16* __restrict__ Vlo,
        float* __restrict__ Otf) {
    extern __shared__ char sm8[];
    const uint32_t sb = smem_u32(sm8);
    const int tid = threadIdx.x, wid = tid >> 5, lane = tid & 31;
    const int qtile = gridDim.x - 1 - blockIdx.x;
    const int h = blockIdx.y, b = blockIdx.z;
    const int kvh = h >> 2;

    const size_t qbase = ((size_t)(b * NH + h) * SEQ + qtile * AQ) * HD;
    const size_t kbase = ((size_t)(b * NKV + kvh) * SEQ) * HD;

    for (int i = tid; i < AQ * 16; i += 256) {
        int row = i >> 4, c = i & 15;
        uint32_t d = sb + row * (ASTR * 2) + c * 16;
        const size_t src = qbase + (size_t)row * HD + c * 8;
        cp16(d, Qhi + src);
        cp16(d + Q_BYTES, Qlo + src);
    }
    {
        uint32_t dst0 = sb + 2 * Q_BYTES;
        for (int i = tid; i < AKT * 16; i += 256) {
            int row = i >> 4, c = i & 15;
            uint32_t d = dst0 + row * (ASTR * 2) + c * 16;
            const size_t src = kbase + (size_t)row * HD + c * 8;
            cp16(d,                Khi + src);
            cp16(d + KV_BYTES,     Klo + src);
            cp16(d + 2 * KV_BYTES, Vhi + src);
            cp16(d + 3 * KV_BYTES, Vlo + src);
        }
    }
    CP_COMMIT();

    float oacc[16][4];
#pragma unroll
    for (int n = 0; n < 16; n++)
#pragma unroll
        for (int q = 0; q < 4; q++) oacc[n][q] = 0.f;
    float m0 = -1e30f, m1 = -1e30f, l0 = 0.f, l1 = 0.f;

    const uint32_t aRow = wid * 16 + (lane & 15);
    const uint32_t aColP = (lane >> 4) * 8;
    const uint32_t qAddr = sb + (aRow * ASTR + aColP) * 2;
    const uint32_t bRowP = (lane & 7) + ((lane >> 4) & 1) * 8;
    const uint32_t bColP = ((lane >> 3) & 1) * 8;
    const uint32_t vRowP = (lane & 7) + ((lane >> 3) & 1) * 8;
    const uint32_t vColP = (lane >> 4) * 8;

    const int nkt = 2 * qtile + 2;
    const int row0g = qtile * AQ + wid * 16 + (lane >> 2);

    for (int kt = 0; kt < nkt; ++kt) {
        const int s = kt & 1;
        CP_WAIT0();
        __syncthreads();
        if (kt + 1 < nkt) {
            uint32_t dst0 = sb + 2 * Q_BYTES + (s ^ 1) * KVBUF;
            const size_t kvoff = kbase + (size_t)(kt + 1) * AKT * HD;
            for (int i = tid; i < AKT * 16; i += 256) {
                int row = i >> 4, c = i & 15;
                uint32_t d = dst0 + row * (ASTR * 2) + c * 16;
                const size_t src = kvoff + (size_t)row * HD + c * 8;
                cp16(d,                Khi + src);
                cp16(d + KV_BYTES,     Klo + src);
                cp16(d + 2 * KV_BYTES, Vhi + src);
                cp16(d + 3 * KV_BYTES, Vlo + src);
            }
            CP_COMMIT();
        }

        const uint32_t kvb = sb + 2 * Q_BYTES + s * KVBUF;

        float sacc[8][4];
#pragma unroll
        for (int n = 0; n < 8; n++)
#pragma unroll
            for (int q = 0; q < 4; q++) sacc[n][q] = 0.f;

#pragma unroll
        for (int ks = 0; ks < 8; ++ks) {
            uint32_t aq[4], aql[4];
            uint32_t qa = qAddr + ks * 32;
            ldsm_x4(aq, qa);
            ldsm_x4(aql, qa + Q_BYTES);
            uint32_t bh[4][4], bl[4][4];
#pragma unroll
            for (int p = 0; p < 4; ++p) {
                uint32_t ba = kvb + ((p * 16 + bRowP) * ASTR + ks * 16 + bColP) * 2;
                ldsm_x4(bh[p], ba);
                ldsm_x4(bl[p], ba + KV_BYTES);
            }
#pragma unroll
            for (int nt = 0; nt < 8; ++nt) {
                uint32_t h0 = bh[nt >> 1][(nt & 1) * 2];
                uint32_t h1 = bh[nt >> 1][(nt & 1) * 2 + 1];
                uint32_t q0 = bl[nt >> 1][(nt & 1) * 2];
                uint32_t q1 = bl[nt >> 1][(nt & 1) * 2 + 1];
                mma_bf16(sacc[nt], aq, h0, h1);
                mma_bf16(sacc[nt], aq, q0, q1);
                mma_bf16(sacc[nt], aql, h0, h1);
            }
        }

        if (kt * AKT + AKT - 1 > qtile * AQ + wid * 16) {
            const int colb = kt * AKT + (lane & 3) * 2;
#pragma unroll
            for (int nt = 0; nt < 8; ++nt) {
                int c0 = colb + nt * 8;
                if (c0 > row0g)         sacc[nt][0] = -1e30f;
                if (c0 + 1 > row0g)     sacc[nt][1] = -1e30f;
                if (c0 > row0g + 8)     sacc[nt][2] = -1e30f;
                if (c0 + 1 > row0g + 8) sacc[nt][3] = -1e30f;
            }
        }

        float mx0 = -1e30f, mx1 = -1e30f;
#pragma unroll
        for (int nt = 0; nt < 8; ++nt) {
            mx0 = fmaxf(mx0, fmaxf(sacc[nt][0], sacc[nt][1]));
            mx1 = fmaxf(mx1, fmaxf(sacc[nt][2], sacc[nt][3]));
        }
        mx0 = fmaxf(mx0, __shfl_xor_sync(0xffffffffu, mx0, 1));
        mx0 = fmaxf(mx0, __shfl_xor_sync(0xffffffffu, mx0, 2));
        mx1 = fmaxf(mx1, __shfl_xor_sync(0xffffffffu, mx1, 1));
        mx1 = fmaxf(mx1, __shfl_xor_sync(0xffffffffu, mx1, 2));
        float nm0 = fmaxf(m0, mx0), nm1 = fmaxf(m1, mx1);
        float r0 = 0.f, r1 = 0.f;
#pragma unroll
        for (int nt = 0; nt < 8; ++nt) {
            sacc[nt][0] = __expf(sacc[nt][0] - nm0);
            sacc[nt][1] = __expf(sacc[nt][1] - nm0);
            sacc[nt][2] = __expf(sacc[nt][2] - nm1);
            sacc[nt][3] = __expf(sacc[nt][3] - nm1);
            r0 += sacc[nt][0] + sacc[nt][1];
            r1 += sacc[nt][2] + sacc[nt][3];
        }
        r0 += __shfl_xor_sync(0xffffffffu, r0, 1);
        r0 += __shfl_xor_sync(0xffffffffu, r0, 2);
        r1 += __shfl_xor_sync(0xffffffffu, r1, 1);
        r1 += __shfl_xor_sync(0xffffffffu, r1, 2);
        float a0 = __expf(m0 - nm0), a1 = __expf(m1 - nm1);
        l0 = l0 * a0 + r0;
        l1 = l1 * a1 + r1;
        m0 = nm0; m1 = nm1;
#pragma unroll
        for (int n = 0; n < 16; ++n) {
            oacc[n][0] *= a0; oacc[n][1] *= a0;
            oacc[n][2] *= a1; oacc[n][3] *= a1;
        }

        uint32_t ph[8][2], pl[8][2];
#pragma unroll
        for (int nt = 0; nt < 8; ++nt) {
            uint32_t u0 = __float_as_uint(sacc[nt][0]);
            uint32_t u1 = __float_as_uint(sacc[nt][1]);
            uint32_t u2 = __float_as_uint(sacc[nt][2]);
            uint32_t u3 = __float_as_uint(sacc[nt][3]);
            ph[nt][0] = __byte_perm(u0, u1, 0x7632);
            ph[nt][1] = __byte_perm(u2, u3, 0x7632);
            float e0 = sacc[nt][0] - __uint_as_float(u0 & 0xFFFF0000u);
            float e1 = sacc[nt][1] - __uint_as_float(u1 & 0xFFFF0000u);
            float e2 = sacc[nt][2] - __uint_as_float(u2 & 0xFFFF0000u);
            float e3 = sacc[nt][3] - __uint_as_float(u3 & 0xFFFF0000u);
            __nv_bfloat162 p01 = __floats2bfloat162_rn(e0, e1);
            __nv_bfloat162 p23 = __floats2bfloat162_rn(e2, e3);
            pl[nt][0] = *reinterpret_cast<uint32_t*>(&p01);
            pl[nt][1] = *reinterpret_cast<uint32_t*>(&p23);
        }

        const uint32_t vbase = kvb + 2 * KV_BYTES;
#pragma unroll
        for (int kk = 0; kk < 4; ++kk) {
            uint32_t pa[4]  = { ph[2 * kk][0], ph[2 * kk][1], ph[2 * kk + 1][0], ph[2 * kk + 1][1] };
            uint32_t pal[4] = { pl[2 * kk][0], pl[2 * kk][1], pl[2 * kk + 1][0], pl[2 * kk + 1][1] };
#pragma unroll
            for (int nt = 0; nt < 8; ++nt) {
                uint32_t va = vbase + ((kk * 16 + vRowP) * ASTR + nt * 16 + vColP) * 2;
                uint32_t vh[4], vl[4];
                ldsm_x4_t(vh, va);
                ldsm_x4_t(vl, va + KV_BYTES);
                mma_bf16(oacc[2 * nt],     pa,  vh[0], vh[1]);
                mma_bf16(oacc[2 * nt],     pa,  vl[0], vl[1]);
                mma_bf16(oacc[2 * nt],     pal, vh[0], vh[1]);
                mma_bf16(oacc[2 * nt + 1], pa,  vh[2], vh[3]);
                mma_bf16(oacc[2 * nt + 1], pa,  vl[2], vl[3]);
                mma_bf16(oacc[2 * nt + 1], pal, vh[2], vh[3]);
            }
        }
    }

    // ---- epilogue: normalize + tf32-round -> fp32 buffer ----
    float inv0 = 1.0f / l0, inv1 = 1.0f / l1;
    const int trow = b * SEQ + row0g;
    const int cc = (lane & 3) * 2;
#pragma unroll
    for (int nt = 0; nt < 16; ++nt) {
        int col = h * HD + nt * 8 + cc;
        uint2 o01 = make_uint2(f2tf32(oacc[nt][0] * inv0), f2tf32(oacc[nt][1] * inv0));
        uint2 o23 = make_uint2(f2tf32(oacc[nt][2] * inv1), f2tf32(oacc[nt][3] * inv1));
        *reinterpret_cast<uint2*>(&Otf[(size_t)trow * HID + col]) = o01;
        *reinterpret_cast<uint2*>(&Otf[(size_t)(trow + 8) * HID + col]) = o23;
    }
}

// ---------------------------------------------------------------------------
extern "C" void kernel_launch(void* const* d_in, const int* in_sizes, int n_in,
                              void* d_out, int out_size) {
    const float* hs    = (const float*)d_in[0];
    const float* w_qkv = (const float*)d_in[1];
    const float* w_o   = (const float*)d_in[2];
    float* out = (float*)d_out;

    float *hstf, *wqtf, *wotf, *atttf;
    __nv_bfloat16 *qhi, *qlo, *khi, *klo, *vhi, *vlo;
    cudaGetSymbolAddress((void**)&hstf, g_hstf);
    cudaGetSymbolAddress((void**)&wqtf, g_wqtf);
    cudaGetSymbolAddress((void**)&wotf, g_wotf);
    cudaGetSymbolAddress((void**)&atttf, g_atttf);
    cudaGetSymbolAddress((void**)&qhi, g_qhi);
    cudaGetSymbolAddress((void**)&qlo, g_qlo);
    cudaGetSymbolAddress((void**)&khi, g_khi);
    cudaGetSymbolAddress((void**)&klo, g_klo);
    cudaGetSymbolAddress((void**)&vhi, g_vhi);
    cudaGetSymbolAddress((void**)&vlo, g_vlo);

    cudaFuncSetAttribute(gemm_tf32, cudaFuncAttributeMaxDynamicSharedMemorySize, TGEMM_SMEM);
    cudaFuncSetAttribute(gemm_qkv_tf32, cudaFuncAttributeMaxDynamicSharedMemorySize, TGEMM_SMEM);
    cudaFuncSetAttribute(attn_mma, cudaFuncAttributeMaxDynamicSharedMemorySize, ATT_SMEM);

    // 0) tf32-round operands (rna — removes truncation bias)
    conv_tf32<<<(TT * HID / 4 + 255) / 256, 256>>>(hs, hstf, TT * HID / 4);
    conv_tf32<<<(QKVD * HID / 4 + 255) / 256, 256>>>(w_qkv, wqtf, QKVD * HID / 4);
    conv_tf32<<<(HID * HID / 4 + 255) / 256, 256>>>(w_o, wotf, HID * HID / 4);

    // 1) QKV projection (tf32 single-pass) + fused RoPE/split epilogue
    {
        dim3 grid(QKVD / TBN, TT / TBM);
        gemm_qkv_tf32<<<grid, 256, TGEMM_SMEM>>>(hstf, wqtf,
                                                 qhi, qlo, khi, klo, vhi, vlo, HID);
    }
    // 2) tensor-core causal GQA attention (bf16x3) -> tf32-rounded fp32
    {
        dim3 grid(SEQ / AQ, NH, NB);
        attn_mma<<<grid, 256, ATT_SMEM>>>(qhi, qlo, khi, klo, vhi, vlo, atttf);
    }
    // 3) output projection (tf32 single-pass)
    {
        dim3 grid(HID / TBN, TT / TBM);
        gemm_tf32<<<grid, 256, TGEMM_SMEM>>>(atttf, wotf, out, TT, HID, HID);
    }
}

// round 17
// speedup vs baseline: 1.5755x; 1.0796x over previous
#include <cuda_runtime.h>
#include <cuda_bf16.h>
#include <math.h>
#include <stdint.h>

#define TT    4096      // BATCH * SEQ tokens
#define HID   4096
#define NH    32
#define NKV   8
#define HD    128
#define QKVD  6144      // (32 + 2*8) * 128
#define SEQ   1024
#define NB    4

// tf32-rounded fp32 operand buffers
__device__ float g_hstf[(size_t)TT * HID];
__device__ float g_wqtf[(size_t)QKVD * HID];
__device__ float g_wotf[(size_t)HID * HID];
__device__ float g_atttf[(size_t)TT * HID];
// split bf16 q/k/v (head-major) for attention
__device__ __nv_bfloat16 g_qhi[(size_t)NB * NH * SEQ * HD];
__device__ __nv_bfloat16 g_qlo[(size_t)NB * NH * SEQ * HD];
__device__ __nv_bfloat16 g_khi[(size_t)NB * NKV * SEQ * HD];
__device__ __nv_bfloat16 g_klo[(size_t)NB * NKV * SEQ * HD];
__device__ __nv_bfloat16 g_vhi[(size_t)NB * NKV * SEQ * HD];
__device__ __nv_bfloat16 g_vlo[(size_t)NB * NKV * SEQ * HD];

// ===========================================================================
// helpers
// ===========================================================================
__device__ __forceinline__ uint32_t smem_u32(const void* p) {
    uint32_t a;
    asm("{ .reg .u64 t; cvta.to.shared.u64 t, %1; cvt.u32.u64 %0, t; }"
        : "=r"(a) : "l"(p));
    return a;
}
__device__ __forceinline__ void ldsm_x4(uint32_t* r, uint32_t addr) {
    asm volatile("ldmatrix.sync.aligned.m8n8.x4.shared.b16 {%0,%1,%2,%3}, [%4];"
                 : "=r"(r[0]), "=r"(r[1]), "=r"(r[2]), "=r"(r[3]) : "r"(addr));
}
__device__ __forceinline__ void ldsm_x4_t(uint32_t* r, uint32_t addr) {
    asm volatile("ldmatrix.sync.aligned.m8n8.x4.trans.shared.b16 {%0,%1,%2,%3}, [%4];"
                 : "=r"(r[0]), "=r"(r[1]), "=r"(r[2]), "=r"(r[3]) : "r"(addr));
}
__device__ __forceinline__ void mma_bf16(float* c, const uint32_t* a,
                                         uint32_t b0, uint32_t b1) {
    asm volatile(
        "mma.sync.aligned.m16n8k16.row.col.f32.bf16.bf16.f32 "
        "{%0,%1,%2,%3}, {%4,%5,%6,%7}, {%8,%9}, {%0,%1,%2,%3};"
        : "+f"(c[0]), "+f"(c[1]), "+f"(c[2]), "+f"(c[3])
        : "r"(a[0]), "r"(a[1]), "r"(a[2]), "r"(a[3]), "r"(b0), "r"(b1));
}
__device__ __forceinline__ void mma_tf32(float* c, const uint32_t* a,
                                         uint32_t b0, uint32_t b1) {
    asm volatile(
        "mma.sync.aligned.m16n8k8.row.col.f32.tf32.tf32.f32 "
        "{%0,%1,%2,%3}, {%4,%5,%6,%7}, {%8,%9}, {%0,%1,%2,%3};"
        : "+f"(c[0]), "+f"(c[1]), "+f"(c[2]), "+f"(c[3])
        : "r"(a[0]), "r"(a[1]), "r"(a[2]), "r"(a[3]), "r"(b0), "r"(b1));
}
__device__ __forceinline__ void cp16(uint32_t dst, const void* src) {
    asm volatile("cp.async.cg.shared.global [%0], [%1], 16;" :: "r"(dst), "l"(src));
}
#define CP_COMMIT() asm volatile("cp.async.commit_group;" ::: "memory")
#define CP_WAIT0()  asm volatile("cp.async.wait_group 0;" ::: "memory")
#define CP_WAIT1()  asm volatile("cp.async.wait_group 1;" ::: "memory")

__device__ __forceinline__ uint32_t f2tf32(float f) {
    uint32_t r;
    asm("cvt.rna.tf32.f32 %0, %1;" : "=r"(r) : "f"(f));
    return r;
}

// ===========================================================================
// conv_tf32: fp32 -> tf32-rounded fp32 (rna).  4 elements per thread.
// ===========================================================================
__global__ __launch_bounds__(256) void conv_tf32(const float* __restrict__ src,
                                                 float* __restrict__ dst, int n4) {
    int i = blockIdx.x * 256 + threadIdx.x;
    if (i >= n4) return;
    float4 f = reinterpret_cast<const float4*>(src)[i];
    uint4 o;
    o.x = f2tf32(f.x);
    o.y = f2tf32(f.y);
    o.z = f2tf32(f.z);
    o.w = f2tf32(f.w);
    reinterpret_cast<uint4*>(dst)[i] = o;
}

// ===========================================================================
// tf32 single-pass GEMM core (NT): C[M,N] = A[M,K] @ B[N,K]^T.
// CTA 128x128, BK=32, 256 threads (8 warps, 4Mx2N), warp tile 32x64.
// 2-stage cp.async, occ 2.  Fragments via ldmatrix (b16 trick on tf32).
// ===========================================================================
#define TBM 128
#define TBN 128
#define TBK 32
#define TSTR 36                         // float stride (144 B row)
#define TTILEB (128 * TSTR * 4)         // 18432 B
#define TSTAGEB (2 * TTILEB)            // 36864 B (A | B)
#define TGEMM_SMEM (2 * TSTAGEB)        // 73728 B

// A ldsm lane address: rows {0-7,8-15} x koff {0,16B}
//   row = (lane&7) + ((lane>>3)&1)*8 ;  kbyte = ((lane>>4)&1)*16
// B ldsm lane address (pair p covers n-tiles 2p,2p+1):
//   row = (lane&7) + ((lane>>4)&1)*8 ;  kbyte = ((lane>>3)&1)*16
#define TF32_MAINLOOP(Ap, Bp, K)                                                  \
    const int r0 = tid >> 3;                                                       \
    const int cc0 = tid & 7;                                                       \
    auto load_stage = [&](uint32_t base, int k0) {                                 \
        _Pragma("unroll")                                                          \
        for (int u = 0; u < 4; ++u) {                                              \
            int row = r0 + u * 32;                                                 \
            uint32_t d = base + row * (TSTR * 4) + cc0 * 16;                       \
            cp16(d, Ap + (size_t)(bm + row) * K + k0 + cc0 * 4);                   \
            cp16(d + TTILEB, Bp + (size_t)(bn + row) * K + k0 + cc0 * 4);          \
        }                                                                          \
    };                                                                             \
    const int NC = K / TBK;                                                        \
    load_stage(sb, 0);                                                             \
    CP_COMMIT();                                                                   \
    const uint32_t aAddr0 = sb                                                     \
        + (wm * 32 + (lane & 7) + ((lane >> 3) & 1) * 8) * (TSTR * 4)              \
        + ((lane >> 4) & 1) * 16;                                                  \
    const uint32_t bAddr0 = sb + TTILEB                                            \
        + (wn * 64 + (lane & 7) + ((lane >> 4) & 1) * 8) * (TSTR * 4)              \
        + ((lane >> 3) & 1) * 16;                                                  \
    for (int kc = 0; kc < NC; ++kc) {                                              \
        if (kc + 1 < NC) {                                                         \
            load_stage(sb + ((kc + 1) & 1) * TSTAGEB, (kc + 1) * TBK);             \
            CP_COMMIT();                                                           \
            CP_WAIT1();                                                            \
        } else {                                                                   \
            CP_WAIT0();                                                            \
        }                                                                          \
        __syncthreads();                                                           \
        const uint32_t soff = (kc & 1) * TSTAGEB;                                  \
        _Pragma("unroll")                                                          \
        for (int k8 = 0; k8 < 4; ++k8) {                                           \
            const uint32_t ko = k8 * 32;  /* 8 floats */                           \
            uint32_t a[2][4];                                                      \
            _Pragma("unroll")                                                      \
            for (int mt = 0; mt < 2; ++mt)                                         \
                ldsm_x4(a[mt], aAddr0 + soff + mt * (16 * TSTR * 4) + ko);         \
            _Pragma("unroll")                                                      \
            for (int p = 0; p < 4; ++p) {                                          \
                uint32_t bq[4];                                                    \
                ldsm_x4(bq, bAddr0 + soff + p * (16 * TSTR * 4) + ko);             \
                mma_tf32(acc[0][2 * p],     a[0], bq[0], bq[1]);                   \
                mma_tf32(acc[1][2 * p],     a[1], bq[0], bq[1]);                   \
                mma_tf32(acc[0][2 * p + 1], a[0], bq[2], bq[3]);                   \
                mma_tf32(acc[1][2 * p + 1], a[1], bq[2], bq[3]);                   \
            }                                                                      \
        }                                                                          \
        __syncthreads();                                                           \
    }

// plain fp32-C epilogue — used for the O-projection
__global__ __launch_bounds__(256, 2) void gemm_tf32(
        const float* __restrict__ A, const float* __restrict__ B,
        float* __restrict__ C, int M, int N, int K) {
    extern __shared__ char sm8[];
    const uint32_t sb = smem_u32(sm8);
    const int tid = threadIdx.x;
    const int wid = tid >> 5;
    const int lane = tid & 31;
    const int wm = wid & 3;
    const int wn = wid >> 2;
    const int bm = blockIdx.y * TBM;
    const int bn = blockIdx.x * TBN;

    float acc[2][8][4];
#pragma unroll
    for (int i = 0; i < 2; i++)
#pragma unroll
        for (int j = 0; j < 8; j++)
#pragma unroll
            for (int q = 0; q < 4; q++) acc[i][j][q] = 0.f;

    TF32_MAINLOOP(A, B, K)

    const int g = lane >> 2;
    const int cc = (lane & 3) * 2;
#pragma unroll
    for (int mt = 0; mt < 2; ++mt) {
        int rowc = bm + wm * 32 + mt * 16 + g;
#pragma unroll
        for (int nt = 0; nt < 8; ++nt) {
            int col = bn + wn * 64 + nt * 8 + cc;
            *reinterpret_cast<float2*>(&C[(size_t)rowc * N + col]) =
                make_float2(acc[mt][nt][0], acc[mt][nt][1]);
            *reinterpret_cast<float2*>(&C[(size_t)(rowc + 8) * N + col]) =
                make_float2(acc[mt][nt][2], acc[mt][nt][3]);
        }
    }
}

// QKV variant: fused RoPE + head-major bf16 hi/lo split epilogue (bn>>7 = head)
__global__ __launch_bounds__(256, 2) void gemm_qkv_tf32(
        const float* __restrict__ A, const float* __restrict__ B,
        __nv_bfloat16* __restrict__ qhi, __nv_bfloat16* __restrict__ qlo,
        __nv_bfloat16* __restrict__ khi, __nv_bfloat16* __restrict__ klo,
        __nv_bfloat16* __restrict__ vhi, __nv_bfloat16* __restrict__ vlo,
        int K) {
    extern __shared__ char sm8[];
    const uint32_t sb = smem_u32(sm8);
    const int tid = threadIdx.x;
    const int wid = tid >> 5;
    const int lane = tid & 31;
    const int wm = wid & 3;
    const int wn = wid >> 2;
    const int bm = blockIdx.y * TBM;
    const int bn = blockIdx.x * TBN;

    float acc[2][8][4];
#pragma unroll
    for (int i = 0; i < 2; i++)
#pragma unroll
        for (int j = 0; j < 8; j++)
#pragma unroll
            for (int q = 0; q < 4; q++) acc[i][j][q] = 0.f;

    TF32_MAINLOOP(A, B, K)

    // stage fp32 tile in smem [128][132]  (67584 B <= 73728 B)
    __syncthreads();
    float* cs = reinterpret_cast<float*>(sm8);
    const int g = lane >> 2;
    const int cc = (lane & 3) * 2;
#pragma unroll
    for (int mt = 0; mt < 2; ++mt) {
        int rowl = wm * 32 + mt * 16 + g;
#pragma unroll
        for (int nt = 0; nt < 8; ++nt) {
            int coll = wn * 64 + nt * 8 + cc;
            *reinterpret_cast<float2*>(&cs[rowl * 132 + coll]) =
                make_float2(acc[mt][nt][0], acc[mt][nt][1]);
            *reinterpret_cast<float2*>(&cs[(rowl + 8) * 132 + coll]) =
                make_float2(acc[mt][nt][2], acc[mt][nt][3]);
        }
    }
    __syncthreads();

    const int hh = bn >> 7;                  // packed head 0..47
    __nv_bfloat16 *dh, *dl;
    if (hh < NH)            { dh = qhi; dl = qlo; }
    else if (hh < NH + NKV) { dh = khi; dl = klo; }
    else                    { dh = vhi; dl = vlo; }
    const bool do_rope = (hh < NH + NKV);
    const bool do_scale = (hh < NH);

#pragma unroll 4
    for (int it = 0; it < 32; ++it) {
        int p = it * 256 + tid;
        int row = p >> 6;
        int i = p & 63;
        float x1 = cs[row * 132 + i];
        float x2 = cs[row * 132 + i + 64];
        int t = bm + row;
        int s = t & (SEQ - 1);
        int b = t >> 10;
        float y1, y2;
        if (do_rope) {
            const float L2T = 13.287712379549449f;   // log2(10000)
            float invf = exp2f(-(float)(2 * i) * (1.0f / (float)HD) * L2T);
            float ang = (float)s * invf;
            float sn, csv;
            sincosf(ang, &sn, &csv);
            y1 = x1 * csv - x2 * sn;
            y2 = x2 * csv + x1 * sn;
        } else { y1 = x1; y2 = x2; }
        if (do_scale) {
            const float sc = 0.08838834764831845f;   // 128^-0.5
            y1 *= sc; y2 *= sc;
        }
        size_t off;
        if (hh < NH)            off = ((size_t)(b * NH + hh) * SEQ + s) * HD;
        else if (hh < NH + NKV) off = ((size_t)(b * NKV + (hh - NH)) * SEQ + s) * HD;
        else                    off = ((size_t)(b * NKV + (hh - NH - NKV)) * SEQ + s) * HD;
        uint32_t u1 = __float_as_uint(y1), u2 = __float_as_uint(y2);
        float h1 = __uint_as_float(u1 & 0xFFFF0000u);
        float h2 = __uint_as_float(u2 & 0xFFFF0000u);
        dh[off + i]      = __float2bfloat16(h1);
        dh[off + i + 64] = __float2bfloat16(h2);
        dl[off + i]      = __float2bfloat16(y1 - h1);
        dl[off + i + 64] = __float2bfloat16(y2 - h2);
    }
}

// ===========================================================================
// Tensor-core causal GQA flash attention (bf16x3 split).
// Epilogue writes tf32-rounded fp32 (feeds O-proj A side).
// ===========================================================================
#define AQ   128
#define AKT  64
#define ASTR 136
#define Q_BYTES   (AQ * ASTR * 2)
#define KV_BYTES  (AKT * ASTR * 2)
#define KVBUF     (4 * KV_BYTES)
#define ATT_SMEM  (2 * Q_BYTES + 2 * KVBUF)

__global__ __launch_bounds__(256) void attn_mma(
        const __nv_bfloat16* __restrict__ Qhi, const __nv_bfloat16* __restrict__ Qlo,
        const __nv_bfloat16* __restrict__ Khi, const __nv_bfloat16* __restrict__ Klo,
        const __nv_bfloat16* __restrict__ Vhi, const __nv_bfloat16* __restrict__ Vlo,
        float* __restrict__ Otf) {
    extern __shared__ char sm8[];
    const uint32_t sb = smem_u32(sm8);
    const int tid = threadIdx.x, wid = tid >> 5, lane = tid & 31;
    const int qtile = gridDim.x - 1 - blockIdx.x;
    const int h = blockIdx.y, b = blockIdx.z;
    const int kvh = h >> 2;

    const size_t qbase = ((size_t)(b * NH + h) * SEQ + qtile * AQ) * HD;
    const size_t kbase = ((size_t)(b * NKV + kvh) * SEQ) * HD;

    for (int i = tid; i < AQ * 16; i += 256) {
        int row = i >> 4, c = i & 15;
        uint32_t d = sb + row * (ASTR * 2) + c * 16;
        const size_t src = qbase + (size_t)row * HD + c * 8;
        cp16(d, Qhi + src);
        cp16(d + Q_BYTES, Qlo + src);
    }
    {
        uint32_t dst0 = sb + 2 * Q_BYTES;
        for (int i = tid; i < AKT * 16; i += 256) {
            int row = i >> 4, c = i & 15;
            uint32_t d = dst0 + row * (ASTR * 2) + c * 16;
            const size_t src = kbase + (size_t)row * HD + c * 8;
            cp16(d,                Khi + src);
            cp16(d + KV_BYTES,     Klo + src);
            cp16(d + 2 * KV_BYTES, Vhi + src);
            cp16(d + 3 * KV_BYTES, Vlo + src);
        }
    }
    CP_COMMIT();

    float oacc[16][4];
#pragma unroll
    for (int n = 0; n < 16; n++)
#pragma unroll
        for (int q = 0; q < 4; q++) oacc[n][q] = 0.f;
    float m0 = -1e30f, m1 = -1e30f, l0 = 0.f, l1 = 0.f;

    const uint32_t aRow = wid * 16 + (lane & 15);
    const uint32_t aColP = (lane >> 4) * 8;
    const uint32_t qAddr = sb + (aRow * ASTR + aColP) * 2;
    const uint32_t bRowP = (lane & 7) + ((lane >> 4) & 1) * 8;
    const uint32_t bColP = ((lane >> 3) & 1) * 8;
    const uint32_t vRowP = (lane & 7) + ((lane >> 3) & 1) * 8;
    const uint32_t vColP = (lane >> 4) * 8;

    const int nkt = 2 * qtile + 2;
    const int row0g = qtile * AQ + wid * 16 + (lane >> 2);

    for (int kt = 0; kt < nkt; ++kt) {
        const int s = kt & 1;
        CP_WAIT0();
        __syncthreads();
        if (kt + 1 < nkt) {
            uint32_t dst0 = sb + 2 * Q_BYTES + (s ^ 1) * KVBUF;
            const size_t kvoff = kbase + (size_t)(kt + 1) * AKT * HD;
            for (int i = tid; i < AKT * 16; i += 256) {
                int row = i >> 4, c = i & 15;
                uint32_t d = dst0 + row * (ASTR * 2) + c * 16;
                const size_t src = kvoff + (size_t)row * HD + c * 8;
                cp16(d,                Khi + src);
                cp16(d + KV_BYTES,     Klo + src);
                cp16(d + 2 * KV_BYTES, Vhi + src);
                cp16(d + 3 * KV_BYTES, Vlo + src);
            }
            CP_COMMIT();
        }

        const uint32_t kvb = sb + 2 * Q_BYTES + s * KVBUF;

        float sacc[8][4];
#pragma unroll
        for (int n = 0; n < 8; n++)
#pragma unroll
            for (int q = 0; q < 4; q++) sacc[n][q] = 0.f;

#pragma unroll
        for (int ks = 0; ks < 8; ++ks) {
            uint32_t aq[4], aql[4];
            uint32_t qa = qAddr + ks * 32;
            ldsm_x4(aq, qa);
            ldsm_x4(aql, qa + Q_BYTES);
            uint32_t bh[4][4], bl[4][4];
#pragma unroll
            for (int p = 0; p < 4; ++p) {
                uint32_t ba = kvb + ((p * 16 + bRowP) * ASTR + ks * 16 + bColP) * 2;
                ldsm_x4(bh[p], ba);
                ldsm_x4(bl[p], ba + KV_BYTES);
            }
#pragma unroll
            for (int nt = 0; nt < 8; ++nt) {
                uint32_t h0 = bh[nt >> 1][(nt & 1) * 2];
                uint32_t h1 = bh[nt >> 1][(nt & 1) * 2 + 1];
                uint32_t q0 = bl[nt >> 1][(nt & 1) * 2];
                uint32_t q1 = bl[nt >> 1][(nt & 1) * 2 + 1];
                mma_bf16(sacc[nt], aq, h0, h1);
                mma_bf16(sacc[nt], aq, q0, q1);
                mma_bf16(sacc[nt], aql, h0, h1);
            }
        }

        if (kt * AKT + AKT - 1 > qtile * AQ + wid * 16) {
            const int colb = kt * AKT + (lane & 3) * 2;
#pragma unroll
            for (int nt = 0; nt < 8; ++nt) {
                int c0 = colb + nt * 8;
                if (c0 > row0g)         sacc[nt][0] = -1e30f;
                if (c0 + 1 > row0g)     sacc[nt][1] = -1e30f;
                if (c0 > row0g + 8)     sacc[nt][2] = -1e30f;
                if (c0 + 1 > row0g + 8) sacc[nt][3] = -1e30f;
            }
        }

        float mx0 = -1e30f, mx1 = -1e30f;
#pragma unroll
        for (int nt = 0; nt < 8; ++nt) {
            mx0 = fmaxf(mx0, fmaxf(sacc[nt][0], sacc[nt][1]));
            mx1 = fmaxf(mx1, fmaxf(sacc[nt][2], sacc[nt][3]));
        }
        mx0 = fmaxf(mx0, __shfl_xor_sync(0xffffffffu, mx0, 1));
        mx0 = fmaxf(mx0, __shfl_xor_sync(0xffffffffu, mx0, 2));
        mx1 = fmaxf(mx1, __shfl_xor_sync(0xffffffffu, mx1, 1));
        mx1 = fmaxf(mx1, __shfl_xor_sync(0xffffffffu, mx1, 2));
        float nm0 = fmaxf(m0, mx0), nm1 = fmaxf(m1, mx1);
        float r0 = 0.f, r1 = 0.f;
#pragma unroll
        for (int nt = 0; nt < 8; ++nt) {
            sacc[nt][0] = __expf(sacc[nt][0] - nm0);
            sacc[nt][1] = __expf(sacc[nt][1] - nm0);
            sacc[nt][2] = __expf(sacc[nt][2] - nm1);
            sacc[nt][3] = __expf(sacc[nt][3] - nm1);
            r0 += sacc[nt][0] + sacc[nt][1];
            r1 += sacc[nt][2] + sacc[nt][3];
        }
        r0 += __shfl_xor_sync(0xffffffffu, r0, 1);
        r0 += __shfl_xor_sync(0xffffffffu, r0, 2);
        r1 += __shfl_xor_sync(0xffffffffu, r1, 1);
        r1 += __shfl_xor_sync(0xffffffffu, r1, 2);
        float a0 = __expf(m0 - nm0), a1 = __expf(m1 - nm1);
        l0 = l0 * a0 + r0;
        l1 = l1 * a1 + r1;
        m0 = nm0; m1 = nm1;
#pragma unroll
        for (int n = 0; n < 16; ++n) {
            oacc[n][0] *= a0; oacc[n][1] *= a0;
            oacc[n][2] *= a1; oacc[n][3] *= a1;
        }

        uint32_t ph[8][2], pl[8][2];
#pragma unroll
        for (int nt = 0; nt < 8; ++nt) {
            uint32_t u0 = __float_as_uint(sacc[nt][0]);
            uint32_t u1 = __float_as_uint(sacc[nt][1]);
            uint32_t u2 = __float_as_uint(sacc[nt][2]);
            uint32_t u3 = __float_as_uint(sacc[nt][3]);
            ph[nt][0] = __byte_perm(u0, u1, 0x7632);
            ph[nt][1] = __byte_perm(u2, u3, 0x7632);
            float e0 = sacc[nt][0] - __uint_as_float(u0 & 0xFFFF0000u);
            float e1 = sacc[nt][1] - __uint_as_float(u1 & 0xFFFF0000u);
            float e2 = sacc[nt][2] - __uint_as_float(u2 & 0xFFFF0000u);
            float e3 = sacc[nt][3] - __uint_as_float(u3 & 0xFFFF0000u);
            __nv_bfloat162 p01 = __floats2bfloat162_rn(e0, e1);
            __nv_bfloat162 p23 = __floats2bfloat162_rn(e2, e3);
            pl[nt][0] = *reinterpret_cast<uint32_t*>(&p01);
            pl[nt][1] = *reinterpret_cast<uint32_t*>(&p23);
        }

        const uint32_t vbase = kvb + 2 * KV_BYTES;
#pragma unroll
        for (int kk = 0; kk < 4; ++kk) {
            uint32_t pa[4]  = { ph[2 * kk][0], ph[2 * kk][1], ph[2 * kk + 1][0], ph[2 * kk + 1][1] };
            uint32_t pal[4] = { pl[2 * kk][0], pl[2 * kk][1], pl[2 * kk + 1][0], pl[2 * kk + 1][1] };
#pragma unroll
            for (int nt = 0; nt < 8; ++nt) {
                uint32_t va = vbase + ((kk * 16 + vRowP) * ASTR + nt * 16 + vColP) * 2;
                uint32_t vh[4], vl[4];
                ldsm_x4_t(vh, va);
                ldsm_x4_t(vl, va + KV_BYTES);
                mma_bf16(oacc[2 * nt],     pa,  vh[0], vh[1]);
                mma_bf16(oacc[2 * nt],     pa,  vl[0], vl[1]);
                mma_bf16(oacc[2 * nt],     pal, vh[0], vh[1]);
                mma_bf16(oacc[2 * nt + 1], pa,  vh[2], vh[3]);
                mma_bf16(oacc[2 * nt + 1], pa,  vl[2], vl[3]);
                mma_bf16(oacc[2 * nt + 1], pal, vh[2], vh[3]);
            }
        }
    }

    // ---- epilogue: normalize + tf32-round -> fp32 buffer ----
    float inv0 = 1.0f / l0, inv1 = 1.0f / l1;
    const int trow = b * SEQ + row0g;
    const int cc = (lane & 3) * 2;
#pragma unroll
    for (int nt = 0; nt < 16; ++nt) {
        int col = h * HD + nt * 8 + cc;
        uint2 o01 = make_uint2(f2tf32(oacc[nt][0] * inv0), f2tf32(oacc[nt][1] * inv0));
        uint2 o23 = make_uint2(f2tf32(oacc[nt][2] * inv1), f2tf32(oacc[nt][3] * inv1));
        *reinterpret_cast<uint2*>(&Otf[(size_t)trow * HID + col]) = o01;
        *reinterpret_cast<uint2*>(&Otf[(size_t)(trow + 8) * HID + col]) = o23;
    }
}

// ---------------------------------------------------------------------------
extern "C" void kernel_launch(void* const* d_in, const int* in_sizes, int n_in,
                              void* d_out, int out_size) {
    const float* hs    = (const float*)d_in[0];
    const float* w_qkv = (const float*)d_in[1];
    const float* w_o   = (const float*)d_in[2];
    float* out = (float*)d_out;

    float *hstf, *wqtf, *wotf, *atttf;
    __nv_bfloat16 *qhi, *qlo, *khi, *klo, *vhi, *vlo;
    cudaGetSymbolAddress((void**)&hstf, g_hstf);
    cudaGetSymbolAddress((void**)&wqtf, g_wqtf);
    cudaGetSymbolAddress((void**)&wotf, g_wotf);
    cudaGetSymbolAddress((void**)&atttf, g_atttf);
    cudaGetSymbolAddress((void**)&qhi, g_qhi);
    cudaGetSymbolAddress((void**)&qlo, g_qlo);
    cudaGetSymbolAddress((void**)&khi, g_khi);
    cudaGetSymbolAddress((void**)&klo, g_klo);
    cudaGetSymbolAddress((void**)&vhi, g_vhi);
    cudaGetSymbolAddress((void**)&vlo, g_vlo);

    cudaFuncSetAttribute(gemm_tf32, cudaFuncAttributeMaxDynamicSharedMemorySize, TGEMM_SMEM);
    cudaFuncSetAttribute(gemm_qkv_tf32, cudaFuncAttributeMaxDynamicSharedMemorySize, TGEMM_SMEM);
    cudaFuncSetAttribute(attn_mma, cudaFuncAttributeMaxDynamicSharedMemorySize, ATT_SMEM);

    // 0) tf32-round operands (rna — removes truncation bias)
    conv_tf32<<<(TT * HID / 4 + 255) / 256, 256>>>(hs, hstf, TT * HID / 4);
    conv_tf32<<<(QKVD * HID / 4 + 255) / 256, 256>>>(w_qkv, wqtf, QKVD * HID / 4);
    conv_tf32<<<(HID * HID / 4 + 255) / 256, 256>>>(w_o, wotf, HID * HID / 4);

    // 1) QKV projection (tf32 single-pass, ldsm frags) + fused RoPE/split
    {
        dim3 grid(QKVD / TBN, TT / TBM);
        gemm_qkv_tf32<<<grid, 256, TGEMM_SMEM>>>(hstf, wqtf,
                                                 qhi, qlo, khi, klo, vhi, vlo, HID);
    }
    // 2) tensor-core causal GQA attention (bf16x3) -> tf32-rounded fp32
    {
        dim3 grid(SEQ / AQ, NH, NB);
        attn_mma<<<grid, 256, ATT_SMEM>>>(qhi, qlo, khi, klo, vhi, vlo, atttf);
    }
    // 3) output projection (tf32 single-pass, ldsm frags)
    {
        dim3 grid(HID / TBN, TT / TBM);
        gemm_tf32<<<grid, 256, TGEMM_SMEM>>>(atttf, wotf, out, TT, HID, HID);
    }
}